// round 1
// baseline (speedup 1.0000x reference)
#include <cuda_runtime.h>

#define BB   2
#define NP   2048
#define KNB  16
#define EPSI 1e-5f

// ------------------------- device scratch -------------------------
__device__ __align__(16) float d_FE0[BB*NP*256];
__device__ __align__(16) float d_FE1[BB*NP*256];
__device__ int   d_KN0[BB*NP*KNB];
__device__ int   d_KN1[BB*NP*KNB];
__device__ __align__(16) float d_CC [BB*NP*1024];
__device__ __align__(16) float d_PQ [BB*NP*1024];
__device__ __align__(16) float d_MX [BB*NP*512];
__device__ __align__(16) float d_SC [8*2048*2048];
__device__ __align__(16) float d_QH [BB*4*NP*64];
__device__ __align__(16) float d_KH [BB*4*NP*64];
__device__ __align__(16) float d_VT [BB*4*64*NP];
__device__ __align__(16) float d_OH [BB*4*NP*64];
__device__ float d_STT[2*BB*1024];
__device__ __align__(16) float d_W1c[512*256];
__device__ __align__(16) float d_W2c[1024*256];

// ------------------------- transpose (B,R,C)->(B,C,R) -------------------------
__global__ void k_transpose(const float* __restrict__ in, float* __restrict__ out,
                            int R, int Cc)
{
    __shared__ float t[32][33];
    int b  = blockIdx.z;
    const float* ip = in  + (long)b * R * Cc;
    float*       op = out + (long)b * R * Cc;
    int c0 = blockIdx.x * 32, r0 = blockIdx.y * 32;
    for (int i = threadIdx.y; i < 32; i += 8)
        t[i][threadIdx.x] = ip[(long)(r0 + i) * Cc + c0 + threadIdx.x];
    __syncthreads();
    for (int i = threadIdx.y; i < 32; i += 8)
        op[(long)(c0 + i) * R + r0 + threadIdx.x] = t[threadIdx.x][i];
}

// ------------------------- kNN (block per point) -------------------------
__global__ void __launch_bounds__(256) k_knn(const float* __restrict__ coords,
                                             int* __restrict__ knn)
{
    __shared__ float sx[NP], sy[NP], sz[NP], sd[NP];
    __shared__ float wv[8];
    __shared__ int   wi[8];
    int b = blockIdx.x / NP;
    int n = blockIdx.x % NP;
    const float* cb = coords + (long)b * 3 * NP;
    for (int j = threadIdx.x; j < NP; j += 256) {
        sx[j] = cb[j]; sy[j] = cb[NP + j]; sz[j] = cb[2 * NP + j];
    }
    __syncthreads();
    float xn = sx[n], yn = sy[n], zn = sz[n];
    float sqn = xn*xn + yn*yn + zn*zn;
    for (int j = threadIdx.x; j < NP; j += 256) {
        float x = sx[j], y = sy[j], z = sz[j];
        float d = sqn + (x*x + y*y + z*z) - 2.f * (xn*x + yn*y + zn*z);
        sd[j] = (j == n) ? 3.4e38f : d;
    }
    __syncthreads();
    int lane = threadIdx.x & 31, warp = threadIdx.x >> 5;
    for (int r = 0; r < KNB; r++) {
        float best = 3.0e38f; int bi = NP;
        for (int j = threadIdx.x; j < NP; j += 256) {
            float v = sd[j];
            if (v < best) { best = v; bi = j; }
        }
        #pragma unroll
        for (int off = 16; off; off >>= 1) {
            float ov = __shfl_down_sync(0xffffffffu, best, off);
            int   oi = __shfl_down_sync(0xffffffffu, bi,   off);
            if (ov < best || (ov == best && oi < bi)) { best = ov; bi = oi; }
        }
        if (lane == 0) { wv[warp] = best; wi[warp] = bi; }
        __syncthreads();
        if (threadIdx.x == 0) {
            float fb = wv[0]; int fi = wi[0];
            for (int w = 1; w < 8; w++)
                if (wv[w] < fb || (wv[w] == fb && wi[w] < fi)) { fb = wv[w]; fi = wi[w]; }
            knn[((long)b * NP + n) * KNB + r] = fi;
            sd[fi] = 3.4e38f;
        }
        __syncthreads();
    }
}

// ------------------------- GEMM: C[m,o] = alpha*sum_k A[m,k]*W[o,k] (+bias) ----
// grid: (Nout/64, M/64, Z); 256 threads; all dims multiples of 64 (K mult of 16).
__global__ void __launch_bounds__(256) k_gemm(
    const float* __restrict__ A, int lda, long sA,
    const float* __restrict__ W, int ldw, long sW,
    const float* __restrict__ bias,
    float* __restrict__ C, int ldc, long sC,
    int K, float alpha)
{
    __shared__ __align__(16) float As[16][68];
    __shared__ __align__(16) float Ws[16][68];
    int lr = threadIdx.x >> 2;
    int lc = (threadIdx.x & 3) << 2;
    int tx = threadIdx.x & 15;
    int ty = threadIdx.x >> 4;
    const float* Ap = A + blockIdx.z * sA + (long)(blockIdx.y * 64 + lr) * lda + lc;
    const float* Wp = W + blockIdx.z * sW + (long)(blockIdx.x * 64 + lr) * ldw + lc;
    float acc[4][4];
    #pragma unroll
    for (int i = 0; i < 4; i++)
        #pragma unroll
        for (int j = 0; j < 4; j++) acc[i][j] = 0.f;

    for (int k0 = 0; k0 < K; k0 += 16) {
        float4 a4 = *(const float4*)(Ap + k0);
        float4 w4 = *(const float4*)(Wp + k0);
        As[lc + 0][lr] = a4.x; As[lc + 1][lr] = a4.y;
        As[lc + 2][lr] = a4.z; As[lc + 3][lr] = a4.w;
        Ws[lc + 0][lr] = w4.x; Ws[lc + 1][lr] = w4.y;
        Ws[lc + 2][lr] = w4.z; Ws[lc + 3][lr] = w4.w;
        __syncthreads();
        #pragma unroll
        for (int kk = 0; kk < 16; kk++) {
            float4 av = *(const float4*)&As[kk][ty * 4];
            float4 wv = *(const float4*)&Ws[kk][tx * 4];
            float aa[4] = {av.x, av.y, av.z, av.w};
            float ww[4] = {wv.x, wv.y, wv.z, wv.w};
            #pragma unroll
            for (int i = 0; i < 4; i++)
                #pragma unroll
                for (int j = 0; j < 4; j++)
                    acc[i][j] += aa[i] * ww[j];
        }
        __syncthreads();
    }
    float* Cp = C + blockIdx.z * sC;
    int obase = blockIdx.x * 64 + tx * 4;
    float bv0 = 0.f, bv1 = 0.f, bv2 = 0.f, bv3 = 0.f;
    if (bias) {
        float4 b4 = *(const float4*)&bias[obase];
        bv0 = b4.x; bv1 = b4.y; bv2 = b4.z; bv3 = b4.w;
    }
    #pragma unroll
    for (int i = 0; i < 4; i++) {
        long m = blockIdx.y * 64 + ty * 4 + i;
        float4 o4;
        o4.x = acc[i][0] * alpha + bv0;
        o4.y = acc[i][1] * alpha + bv1;
        o4.z = acc[i][2] * alpha + bv2;
        o4.w = acc[i][3] * alpha + bv3;
        *(float4*)&Cp[m * ldc + obase] = o4;
    }
}

// ------------------------- weight prep: stacked [Wa-Wb; Wb] -------------------
__global__ void k_prepw(const float* __restrict__ W, float* __restrict__ Wc,
                        int O, int Ci)
{
    long i = blockIdx.x * (long)blockDim.x + threadIdx.x;
    if (i >= (long)O * Ci) return;
    int o = (int)(i / Ci), c = (int)(i % Ci);
    float a = W[(long)o * 2 * Ci + c];
    float bq = W[(long)o * 2 * Ci + Ci + c];
    Wc[(long)o * Ci + c]        = a - bq;
    Wc[((long)O + o) * Ci + c]  = bq;
}

// ------------------------- strided copy -------------------------
__global__ void k_copy(const float* __restrict__ src, int lds,
                       float* __restrict__ dst, int ldd, long rows, int cols)
{
    long i = blockIdx.x * (long)blockDim.x + threadIdx.x;
    if (i >= rows * (long)cols) return;
    long r = i / cols; int c = (int)(i % cols);
    dst[r * ldd + c] = src[r * lds + c];
}

// ------------------------- edge gather: max + stats -------------------------
__global__ void __launch_bounds__(256) k_edge(const float* __restrict__ PQ,
                                              const int* __restrict__ knn,
                                              float* __restrict__ mx,
                                              float* __restrict__ ssum,
                                              float* __restrict__ sssq,
                                              int Co)
{
    __shared__ long nbb[KNB];
    long bn = blockIdx.x;               // b*NP + n
    int  b  = (int)(bn / NP);
    if (threadIdx.x < KNB) {
        int nb = knn[bn * KNB + threadIdx.x];
        nbb[threadIdx.x] = ((long)b * NP + nb) * (2 * Co) + Co;
    }
    __syncthreads();
    const float* Prow = PQ + bn * (2 * Co);
    for (int o = threadIdx.x; o < Co; o += 256) {
        float p = Prow[o];
        float mv = -3.4e38f, s = 0.f, ss = 0.f;
        #pragma unroll
        for (int k2 = 0; k2 < KNB; k2++) {
            float v = p + PQ[nbb[k2] + o];
            mv = fmaxf(mv, v); s += v; ss += v * v;
        }
        mx[bn * Co + o] = mv;
        atomicAdd(&ssum[b * 1024 + o], s);
        atomicAdd(&sssq[b * 1024 + o], ss);
    }
}

// ------------------------- per-channel stats over N -------------------------
__global__ void __launch_bounds__(256) k_colsum(const float* __restrict__ X, int ldx,
                                                float* __restrict__ ssum,
                                                float* __restrict__ sssq, int Co)
{
    int nch = NP / 128;
    int b  = blockIdx.x / nch;
    int ch = blockIdx.x % nch;
    long r0 = (long)b * NP + ch * 128;
    for (int o = threadIdx.x; o < Co; o += 256) {
        float s = 0.f, ss = 0.f;
        for (int r = 0; r < 128; r++) {
            float v = X[(r0 + r) * ldx + o];
            s += v; ss += v * v;
        }
        atomicAdd(&ssum[b * 1024 + o], s);
        atomicAdd(&sssq[b * 1024 + o], ss);
    }
}

// ------------------------- normalize + activation -------------------------
// act: 1 = leaky relu(0.2), 2 = relu
__global__ void k_norm_act(const float* __restrict__ X, int ldx, int offx,
                           float* __restrict__ Y, int ldy, int offy,
                           const float* __restrict__ ssum,
                           const float* __restrict__ sssq,
                           int Co, float invcnt, int act)
{
    long i = blockIdx.x * (long)blockDim.x + threadIdx.x;
    long total = (long)BB * NP * Co;
    if (i >= total) return;
    int  o  = (int)(i % Co);
    long rn = i / Co;
    int  b  = (int)(rn / NP);
    float mu  = ssum[b * 1024 + o] * invcnt;
    float var = sssq[b * 1024 + o] * invcnt - mu * mu;
    float v = (X[rn * ldx + offx + o] - mu) * rsqrtf(var + EPSI);
    if (act == 1) v = (v >= 0.f) ? v : 0.2f * v;
    else          v = (v > 0.f)  ? v : 0.f;
    Y[rn * ldy + offy + o] = v;
}

// ------------------------- softmax over rows of 2048 -------------------------
__global__ void __launch_bounds__(256) k_softmax(float* __restrict__ S)
{
    __shared__ float row[2048];
    __shared__ float red[8];
    float* rp = S + (long)blockIdx.x * 2048;
    int tid = threadIdx.x;
    float mx = -3.4e38f;
    for (int j = tid; j < 2048; j += 256) { float v = rp[j]; row[j] = v; mx = fmaxf(mx, v); }
    #pragma unroll
    for (int off = 16; off; off >>= 1) mx = fmaxf(mx, __shfl_xor_sync(0xffffffffu, mx, off));
    if ((tid & 31) == 0) red[tid >> 5] = mx;
    __syncthreads();
    mx = red[0];
    #pragma unroll
    for (int w = 1; w < 8; w++) mx = fmaxf(mx, red[w]);
    __syncthreads();
    float s = 0.f;
    for (int j = tid; j < 2048; j += 256) { float e = expf(row[j] - mx); row[j] = e; s += e; }
    #pragma unroll
    for (int off = 16; off; off >>= 1) s += __shfl_xor_sync(0xffffffffu, s, off);
    if ((tid & 31) == 0) red[tid >> 5] = s;
    __syncthreads();
    s = 0.f;
    #pragma unroll
    for (int w = 0; w < 8; w++) s += red[w];
    float inv = 1.f / s;
    for (int j = tid; j < 2048; j += 256) rp[j] = row[j] * inv;
}

// ------------------------- attention permutes -------------------------
__global__ void k_perm_qk(const float* __restrict__ raw, float* __restrict__ out)
{
    long i = blockIdx.x * (long)blockDim.x + threadIdx.x;
    if (i >= (long)BB * NP * 256) return;
    int c = (int)(i % 256); long bn = i / 256;
    int n = (int)(bn % NP); int b = (int)(bn / NP);
    int h = c & 3, dd = c >> 2;
    out[(((long)b * 4 + h) * NP + n) * 64 + dd] = raw[i];
}
__global__ void k_perm_v(const float* __restrict__ raw, float* __restrict__ out)
{
    long i = blockIdx.x * (long)blockDim.x + threadIdx.x;
    if (i >= (long)BB * NP * 256) return;
    int c = (int)(i % 256); long bn = i / 256;
    int n = (int)(bn % NP); int b = (int)(bn / NP);
    int h = c & 3, dd = c >> 2;
    out[(((long)b * 4 + h) * 64 + dd) * NP + n] = raw[i];
}
__global__ void k_perm_o(const float* __restrict__ OH, float* __restrict__ out)
{
    long i = blockIdx.x * (long)blockDim.x + threadIdx.x;
    if (i >= (long)BB * NP * 256) return;
    int c = (int)(i % 256); long bn = i / 256;
    int n = (int)(bn % NP); int b = (int)(bn / NP);
    int h = c & 3, dd = c >> 2;
    out[i] = OH[(((long)b * 4 + h) * NP + n) * 64 + dd];
}

// ------------------------- host orchestration -------------------------
static void gemm(const float* A, int lda, long sA,
                 const float* W, int ldw, long sW,
                 const float* bias, float* C, int ldc, long sC,
                 int M, int Nout, int K, float alpha, int Z)
{
    dim3 g(Nout / 64, M / 64, Z);
    k_gemm<<<g, 256>>>(A, lda, sA, W, ldw, sW, bias, C, ldc, sC, K, alpha);
}

extern "C" void kernel_launch(void* const* d_in, const int* in_sizes, int n_in,
                              void* d_out, int out_size)
{
    const float* coords1 = (const float*)d_in[0];
    const float* feats1  = (const float*)d_in[1];
    const float* coords2 = (const float*)d_in[2];
    const float* feats2  = (const float*)d_in[3];
    const float* gW1 = (const float*)d_in[4];
    const float* gW2 = (const float*)d_in[5];
    const float* gW3 = (const float*)d_in[6];
    const float* Wq  = (const float*)d_in[7];  const float* bq  = (const float*)d_in[8];
    const float* Wk  = (const float*)d_in[9];  const float* bk  = (const float*)d_in[10];
    const float* Wv  = (const float*)d_in[11]; const float* bv  = (const float*)d_in[12];
    const float* Wo  = (const float*)d_in[13]; const float* bo  = (const float*)d_in[14];
    const float* Wm1 = (const float*)d_in[15]; const float* bm1 = (const float*)d_in[16];
    const float* Wm2 = (const float*)d_in[17]; const float* bm2 = (const float*)d_in[18];
    float* out = (float*)d_out;

    void* pv;
    float *FE[2]; int *KN[2];
    cudaGetSymbolAddress(&pv, d_FE0); FE[0] = (float*)pv;
    cudaGetSymbolAddress(&pv, d_FE1); FE[1] = (float*)pv;
    cudaGetSymbolAddress(&pv, d_KN0); KN[0] = (int*)pv;
    cudaGetSymbolAddress(&pv, d_KN1); KN[1] = (int*)pv;
    cudaGetSymbolAddress(&pv, d_CC);  float* CCp = (float*)pv;
    cudaGetSymbolAddress(&pv, d_PQ);  float* PQp = (float*)pv;
    cudaGetSymbolAddress(&pv, d_MX);  float* MXp = (float*)pv;
    cudaGetSymbolAddress(&pv, d_SC);  float* SCp = (float*)pv;
    cudaGetSymbolAddress(&pv, d_QH);  float* QHp = (float*)pv;
    cudaGetSymbolAddress(&pv, d_KH);  float* KHp = (float*)pv;
    cudaGetSymbolAddress(&pv, d_VT);  float* VTp = (float*)pv;
    cudaGetSymbolAddress(&pv, d_OH);  float* OHp = (float*)pv;
    cudaGetSymbolAddress(&pv, d_STT); float* STp = (float*)pv;
    cudaGetSymbolAddress(&pv, d_W1c); float* W1c = (float*)pv;
    cudaGetSymbolAddress(&pv, d_W2c); float* W2c = (float*)pv;
    float* SUM = STp;
    float* SSQ = STp + BB * 1024;

    const long M4   = (long)BB * NP;          // 4096 rows
    const int  EWB  = 256;
    dim3 tb(32, 8);

    // inputs -> (B,N,C) layout
    k_transpose<<<dim3(NP / 32, 256 / 32, BB), tb>>>(feats1, FE[0], 256, NP);
    k_transpose<<<dim3(NP / 32, 256 / 32, BB), tb>>>(feats2, FE[1], 256, NP);
    // kNN (coords are constant across layers)
    k_knn<<<BB * NP, 256>>>(coords1, KN[0]);
    k_knn<<<BB * NP, 256>>>(coords2, KN[1]);

    for (int li = 0; li < 4; li++) {
        int i = li / 2;
        if ((li & 1) == 0) {
            // ---------------- GCN layer i, both clouds ----------------
            k_prepw<<<(256 * 256 + 255) / 256, 256>>>(gW1 + (long)i * 256 * 512, W1c, 256, 256);
            k_prepw<<<(512 * 256 + 255) / 256, 256>>>(gW2 + (long)i * 512 * 512, W2c, 512, 256);
            for (int cl = 0; cl < 2; cl++) {
                long tot;
                // concat slot 0: original feats
                tot = M4 * 256;
                k_copy<<<(tot + EWB - 1) / EWB, EWB>>>(FE[cl], 256, CCp, 1024, M4, 256);
                // sublayer 1: PQ = [Wa-Wb; Wb] @ feats
                gemm(FE[cl], 256, 0, W1c, 256, 0, nullptr, PQp, 512, 0, (int)M4, 512, 256, 1.f, 1);
                cudaMemsetAsync(STp, 0, sizeof(float) * 2 * BB * 1024, 0);
                k_edge<<<BB * NP, 256>>>(PQp, KN[cl], MXp, SUM, SSQ, 256);
                tot = M4 * 256;
                k_norm_act<<<(tot + EWB - 1) / EWB, EWB>>>(MXp, 256, 0, CCp, 1024, 256,
                                                           SUM, SSQ, 256, 1.f / 32768.f, 1);
                // sublayer 2 on f1 (CC cols 256:512)
                gemm(CCp + 256, 1024, 0, W2c, 256, 0, nullptr, PQp, 1024, 0, (int)M4, 1024, 256, 1.f, 1);
                cudaMemsetAsync(STp, 0, sizeof(float) * 2 * BB * 1024, 0);
                k_edge<<<BB * NP, 256>>>(PQp, KN[cl], MXp, SUM, SSQ, 512);
                tot = M4 * 512;
                k_norm_act<<<(tot + EWB - 1) / EWB, EWB>>>(MXp, 512, 0, CCp, 1024, 512,
                                                           SUM, SSQ, 512, 1.f / 32768.f, 1);
                // W3 on concat (1024 ch) -> temp (MX), then inorm+lrelu -> FE
                gemm(CCp, 1024, 0, gW3 + (long)i * 256 * 1024, 1024, 0, nullptr,
                     MXp, 256, 0, (int)M4, 256, 1024, 1.f, 1);
                cudaMemsetAsync(STp, 0, sizeof(float) * 2 * BB * 1024, 0);
                k_colsum<<<BB * (NP / 128), 256>>>(MXp, 256, SUM, SSQ, 256);
                tot = M4 * 256;
                k_norm_act<<<(tot + EWB - 1) / EWB, EWB>>>(MXp, 256, 0, FE[cl], 256, 0,
                                                           SUM, SSQ, 256, 1.f / (float)NP, 1);
            }
        } else {
            // ---------------- cross-attention layer i ----------------
            for (int a = 0; a < 2; a++) {
                const float* f1p = FE[a];
                const float* f2p = FE[1 - a];
                long tot = M4 * 256;
                // q / k / v projections + head permutes
                gemm(f1p, 256, 0, Wq + (long)i * 65536, 256, 0, bq + (long)i * 256,
                     MXp, 256, 0, (int)M4, 256, 256, 1.f, 1);
                k_perm_qk<<<(tot + EWB - 1) / EWB, EWB>>>(MXp, QHp);
                gemm(f2p, 256, 0, Wk + (long)i * 65536, 256, 0, bk + (long)i * 256,
                     MXp, 256, 0, (int)M4, 256, 256, 1.f, 1);
                k_perm_qk<<<(tot + EWB - 1) / EWB, EWB>>>(MXp, KHp);
                gemm(f2p, 256, 0, Wv + (long)i * 65536, 256, 0, bv + (long)i * 256,
                     MXp, 256, 0, (int)M4, 256, 256, 1.f, 1);
                k_perm_v<<<(tot + EWB - 1) / EWB, EWB>>>(MXp, VTp);
                // scores = Q K^T / 8  (z = 8 batched heads)
                gemm(QHp, 64, (long)NP * 64, KHp, 64, (long)NP * 64, nullptr,
                     SCp, 2048, (long)2048 * 2048, 2048, 2048, 64, 0.125f, 8);
                k_softmax<<<8 * 2048, 256>>>(SCp);
                // O = attn @ V
                gemm(SCp, 2048, (long)2048 * 2048, VTp, 2048, (long)64 * NP, nullptr,
                     OHp, 64, (long)NP * 64, 2048, 64, 2048, 1.f, 8);
                k_perm_o<<<(tot + EWB - 1) / EWB, EWB>>>(OHp, MXp);
                // concat [f1, Wo(attn)+bo] into CC (width 512)
                k_copy<<<(tot + EWB - 1) / EWB, EWB>>>(f1p, 256, CCp, 512, M4, 256);
                gemm(MXp, 256, 0, Wo + (long)i * 65536, 256, 0, bo + (long)i * 256,
                     CCp + 256, 512, 0, (int)M4, 256, 256, 1.f, 1);
                // Wm1 -> inorm -> relu -> Wm2 -> FE[a]
                gemm(CCp, 512, 0, Wm1 + (long)i * 262144, 512, 0, bm1 + (long)i * 512,
                     PQp, 512, 0, (int)M4, 512, 512, 1.f, 1);
                cudaMemsetAsync(STp, 0, sizeof(float) * 2 * BB * 1024, 0);
                k_colsum<<<BB * (NP / 128), 256>>>(PQp, 512, SUM, SSQ, 512);
                tot = M4 * 512;
                k_norm_act<<<(tot + EWB - 1) / EWB, EWB>>>(PQp, 512, 0, PQp, 512, 0,
                                                           SUM, SSQ, 512, 1.f / (float)NP, 2);
                gemm(PQp, 512, 0, Wm2 + (long)i * 131072, 512, 0, bm2 + (long)i * 256,
                     FE[a], 256, 0, (int)M4, 256, 512, 1.f, 1);
            }
        }
    }

    // outputs back to (B,C,N), concat [feats1, feats2]
    k_transpose<<<dim3(256 / 32, NP / 32, BB), tb>>>(FE[0], out, NP, 256);
    k_transpose<<<dim3(256 / 32, NP / 32, BB), tb>>>(FE[1], out + (long)BB * 256 * NP, NP, 256);
}

// round 3
// speedup vs baseline: 1.3990x; 1.3990x over previous
#include <cuda_runtime.h>
#include <cuda_bf16.h>
#include <cstdint>

#define BB   2
#define NP   2048
#define KNB  16
#define EPSI 1e-5f

// ======================= helpers =======================
__device__ __forceinline__ void split2(float x, __nv_bfloat16& h, __nv_bfloat16& l){
    h = __float2bfloat16(x);
    l = __float2bfloat16(x - __bfloat162float(h));
}
__device__ __forceinline__ uint32_t packbf(__nv_bfloat16 a, __nv_bfloat16 b){
    return ((uint32_t)__bfloat16_as_ushort(b) << 16) | (uint32_t)__bfloat16_as_ushort(a);
}

#define MMA16816(d, a, b) \
    asm volatile("mma.sync.aligned.m16n8k16.row.col.f32.bf16.bf16.f32 " \
        "{%0,%1,%2,%3}, {%4,%5,%6,%7}, {%8,%9}, {%0,%1,%2,%3};" \
        : "+f"((d)[0]), "+f"((d)[1]), "+f"((d)[2]), "+f"((d)[3]) \
        : "r"((a)[0]), "r"((a)[1]), "r"((a)[2]), "r"((a)[3]), \
          "r"((b)[0]), "r"((b)[1]))

// ======================= device scratch =======================
__device__ __align__(16) float d_FE0[BB*NP*256];
__device__ __align__(16) float d_FE1[BB*NP*256];
__device__ int   d_KN0[BB*NP*KNB];
__device__ int   d_KN1[BB*NP*KNB];
__device__ __align__(16) float d_CC [BB*NP*1024];
__device__ __align__(16) float d_PQ [BB*NP*1024];
__device__ __align__(16) float d_MX [BB*NP*512];
__device__ __align__(16) float d_SC [8*2048*2048];
__device__ __align__(16) float d_OH [BB*4*NP*64];
__device__ float d_STT[2*BB*1024];
__device__ __align__(16) __nv_bfloat16 d_AH [BB*NP*1024];
__device__ __align__(16) __nv_bfloat16 d_AL [BB*NP*1024];
__device__ __align__(16) __nv_bfloat16 d_WH [1024*256];
__device__ __align__(16) __nv_bfloat16 d_WL [1024*256];
__device__ __align__(16) __nv_bfloat16 d_QHH[BB*4*NP*64];
__device__ __align__(16) __nv_bfloat16 d_QHL[BB*4*NP*64];
__device__ __align__(16) __nv_bfloat16 d_KHH[BB*4*NP*64];
__device__ __align__(16) __nv_bfloat16 d_KHL[BB*4*NP*64];
__device__ __align__(16) __nv_bfloat16 d_VTH[BB*4*64*NP];
__device__ __align__(16) __nv_bfloat16 d_VTL[BB*4*64*NP];
__device__ __align__(16) __nv_bfloat16 d_SCH[8*2048*2048];
__device__ __align__(16) __nv_bfloat16 d_SCL[8*2048*2048];

// ======================= transpose =======================
__global__ void k_transpose(const float* __restrict__ in, float* __restrict__ out,
                            int R, int Cc)
{
    __shared__ float t[32][33];
    int b  = blockIdx.z;
    const float* ip = in  + (long)b * R * Cc;
    float*       op = out + (long)b * R * Cc;
    int c0 = blockIdx.x * 32, r0 = blockIdx.y * 32;
    for (int i = threadIdx.y; i < 32; i += 8)
        t[i][threadIdx.x] = ip[(long)(r0 + i) * Cc + c0 + threadIdx.x];
    __syncthreads();
    for (int i = threadIdx.y; i < 32; i += 8)
        op[(long)(c0 + i) * R + r0 + threadIdx.x] = t[threadIdx.x][i];
}

// ======================= kNN =======================
__global__ void __launch_bounds__(256) k_knn(const float* __restrict__ coords,
                                             int* __restrict__ knn)
{
    __shared__ float sx[NP], sy[NP], sz[NP], sd[NP];
    __shared__ float wv[8];
    __shared__ int   wi[8];
    int b = blockIdx.x / NP;
    int n = blockIdx.x % NP;
    const float* cb = coords + (long)b * 3 * NP;
    for (int j = threadIdx.x; j < NP; j += 256) {
        sx[j] = cb[j]; sy[j] = cb[NP + j]; sz[j] = cb[2 * NP + j];
    }
    __syncthreads();
    float xn = sx[n], yn = sy[n], zn = sz[n];
    float sqn = xn*xn + yn*yn + zn*zn;
    for (int j = threadIdx.x; j < NP; j += 256) {
        float x = sx[j], y = sy[j], z = sz[j];
        float d = sqn + (x*x + y*y + z*z) - 2.f * (xn*x + yn*y + zn*z);
        sd[j] = (j == n) ? 3.4e38f : d;
    }
    __syncthreads();
    int lane = threadIdx.x & 31, warp = threadIdx.x >> 5;
    for (int r = 0; r < KNB; r++) {
        float best = 3.0e38f; int bi = NP;
        for (int j = threadIdx.x; j < NP; j += 256) {
            float v = sd[j];
            if (v < best) { best = v; bi = j; }
        }
        #pragma unroll
        for (int off = 16; off; off >>= 1) {
            float ov = __shfl_down_sync(0xffffffffu, best, off);
            int   oi = __shfl_down_sync(0xffffffffu, bi,   off);
            if (ov < best || (ov == best && oi < bi)) { best = ov; bi = oi; }
        }
        if (lane == 0) { wv[warp] = best; wi[warp] = bi; }
        __syncthreads();
        if (threadIdx.x == 0) {
            float fb = wv[0]; int fi = wi[0];
            for (int w = 1; w < 8; w++)
                if (wv[w] < fb || (wv[w] == fb && wi[w] < fi)) { fb = wv[w]; fi = wi[w]; }
            knn[((long)b * NP + n) * KNB + r] = fi;
            sd[fi] = 3.4e38f;
        }
        __syncthreads();
    }
}

// ======================= HMMA GEMM (warp-level mma.sync, bf16 hi/lo split) ====
// C[m,o] = alpha * sum_k (AH+AL)[m,k]*(WH+WL)[o,k] + bias[o]
// Tile 128 x BN x 64, 256 threads (8 warps).
// Smem tiles padded to 144B row stride (72 bf16) -> conflict-free lds.b32 frags.
template <int BN>
__global__ void __launch_bounds__(256) mma_gemm(
    const __nv_bfloat16* __restrict__ AH, const __nv_bfloat16* __restrict__ AL,
    long lda, long sA,
    const __nv_bfloat16* __restrict__ WH, const __nv_bfloat16* __restrict__ WL,
    long ldw, long sW,
    const float* __restrict__ bias, float alpha,
    float* __restrict__ C, int ldc, long sC, int K)
{
    constexpr int MT = (BN == 128) ? 4 : 2;   // m16 tiles per warp
    constexpr int NT = 4;                     // n8 tiles per warp
    extern __shared__ __align__(16) char smem[];
    char* sAh = smem;                         // [128][144B]
    char* sAl = smem + 128 * 144;
    char* sWh = smem + 2 * 128 * 144;         // [BN][144B]
    char* sWl = smem + 2 * 128 * 144 + BN * 144;

    int tid = threadIdx.x, wid = tid >> 5, lane = tid & 31;
    int g = lane >> 2, tg = lane & 3;
    int wm = (BN == 128) ? (wid >> 2) * 64 : (wid >> 1) * 32;
    int wn = (BN == 128) ? (wid & 3) * 32 : (wid & 1) * 32;

    long m0 = (long)blockIdx.y * 128;
    int  n0 = blockIdx.x * BN;
    int  z  = blockIdx.z;
    const __nv_bfloat16* pAH = AH + (long)z * sA + m0 * lda;
    const __nv_bfloat16* pAL = AL + (long)z * sA + m0 * lda;
    const __nv_bfloat16* pWH = WH + (long)z * sW + (long)n0 * ldw;
    const __nv_bfloat16* pWL = WL + (long)z * sW + (long)n0 * ldw;

    float acc[MT][NT][4];
    #pragma unroll
    for (int mt = 0; mt < MT; mt++)
        #pragma unroll
        for (int nt = 0; nt < NT; nt++)
            #pragma unroll
            for (int q = 0; q < 4; q++) acc[mt][nt][q] = 0.f;

    for (int k0 = 0; k0 < K; k0 += 64) {
        // stage A tiles (128 rows x 64 bf16)
        #pragma unroll
        for (int it = 0; it < 4; it++) {
            int i = tid + it * 256;
            int r = i >> 3, q = i & 7;
            *(uint4*)(sAh + r * 144 + q * 16) = *(const uint4*)(pAH + (long)r * lda + k0 + q * 8);
            *(uint4*)(sAl + r * 144 + q * 16) = *(const uint4*)(pAL + (long)r * lda + k0 + q * 8);
        }
        // stage W tiles (BN rows x 64 bf16)
        #pragma unroll
        for (int i = tid; i < BN * 8; i += 256) {
            int r = i >> 3, q = i & 7;
            *(uint4*)(sWh + r * 144 + q * 16) = *(const uint4*)(pWH + (long)r * ldw + k0 + q * 8);
            *(uint4*)(sWl + r * 144 + q * 16) = *(const uint4*)(pWL + (long)r * ldw + k0 + q * 8);
        }
        __syncthreads();

        #pragma unroll
        for (int ks = 0; ks < 4; ks++) {
            int kb = ks * 16;
            uint32_t ah[MT][4], al[MT][4];
            #pragma unroll
            for (int mt = 0; mt < MT; mt++) {
                int roff = (wm + mt * 16 + g) * 144 + (kb + tg * 2) * 2;
                ah[mt][0] = *(const uint32_t*)(sAh + roff);
                ah[mt][1] = *(const uint32_t*)(sAh + roff + 8 * 144);
                ah[mt][2] = *(const uint32_t*)(sAh + roff + 16);
                ah[mt][3] = *(const uint32_t*)(sAh + roff + 8 * 144 + 16);
                al[mt][0] = *(const uint32_t*)(sAl + roff);
                al[mt][1] = *(const uint32_t*)(sAl + roff + 8 * 144);
                al[mt][2] = *(const uint32_t*)(sAl + roff + 16);
                al[mt][3] = *(const uint32_t*)(sAl + roff + 8 * 144 + 16);
            }
            uint32_t bh[NT][2], bl[NT][2];
            #pragma unroll
            for (int nt = 0; nt < NT; nt++) {
                int roff = (wn + nt * 8 + g) * 144 + (kb + tg * 2) * 2;
                bh[nt][0] = *(const uint32_t*)(sWh + roff);
                bh[nt][1] = *(const uint32_t*)(sWh + roff + 16);
                bl[nt][0] = *(const uint32_t*)(sWl + roff);
                bl[nt][1] = *(const uint32_t*)(sWl + roff + 16);
            }
            #pragma unroll
            for (int mt = 0; mt < MT; mt++)
                #pragma unroll
                for (int nt = 0; nt < NT; nt++) {
                    MMA16816(acc[mt][nt], ah[mt], bh[nt]);
                    MMA16816(acc[mt][nt], ah[mt], bl[nt]);
                    MMA16816(acc[mt][nt], al[mt], bh[nt]);
                }
        }
        __syncthreads();
    }

    // epilogue
    float* Cz = C + (long)z * sC;
    #pragma unroll
    for (int mt = 0; mt < MT; mt++) {
        long row = m0 + wm + mt * 16 + g;
        #pragma unroll
        for (int nt = 0; nt < NT; nt++) {
            int col = n0 + wn + nt * 8 + tg * 2;
            float b0 = 0.f, b1 = 0.f;
            if (bias) { b0 = __ldg(&bias[col]); b1 = __ldg(&bias[col + 1]); }
            float2 v0, v1;
            v0.x = acc[mt][nt][0] * alpha + b0;
            v0.y = acc[mt][nt][1] * alpha + b1;
            v1.x = acc[mt][nt][2] * alpha + b0;
            v1.y = acc[mt][nt][3] * alpha + b1;
            *(float2*)(Cz + row * (long)ldc + col)       = v0;
            *(float2*)(Cz + (row + 8) * (long)ldc + col) = v1;
        }
    }
}

// ======================= fp32 -> bf16 hi/lo split =======================
__global__ void k_cvt(const float* __restrict__ src, long lda, int K, long total,
                      __nv_bfloat16* __restrict__ H, __nv_bfloat16* __restrict__ L)
{
    long i = ((long)blockIdx.x * blockDim.x + threadIdx.x) * 4;
    if (i >= total) return;
    long r = i / K; int c = (int)(i - r * K);
    float4 v = *(const float4*)(src + r * lda + c);
    __nv_bfloat16 h0,h1,h2,h3,l0,l1,l2,l3;
    split2(v.x,h0,l0); split2(v.y,h1,l1); split2(v.z,h2,l2); split2(v.w,h3,l3);
    *(uint2*)(H + i) = make_uint2(packbf(h0,h1), packbf(h2,h3));
    *(uint2*)(L + i) = make_uint2(packbf(l0,l1), packbf(l2,l3));
}

// weight prep: stacked [Wa-Wb; Wb], split to bf16 hi/lo
__global__ void k_prepw_b(const float* __restrict__ W,
                          __nv_bfloat16* __restrict__ H, __nv_bfloat16* __restrict__ L,
                          int O, int Ci)
{
    long i = blockIdx.x * (long)blockDim.x + threadIdx.x;
    if (i >= (long)O * Ci) return;
    int o = (int)(i / Ci), c = (int)(i % Ci);
    float a  = W[(long)o * 2 * Ci + c];
    float bq = W[(long)o * 2 * Ci + Ci + c];
    __nv_bfloat16 h, l;
    split2(a - bq, h, l);
    H[(long)o * Ci + c] = h; L[(long)o * Ci + c] = l;
    split2(bq, h, l);
    H[((long)O + o) * Ci + c] = h; L[((long)O + o) * Ci + c] = l;
}

// ======================= strided copy =======================
__global__ void k_copy(const float* __restrict__ src, int lds,
                       float* __restrict__ dst, int ldd, long rows, int cols)
{
    long i = blockIdx.x * (long)blockDim.x + threadIdx.x;
    if (i >= rows * (long)cols) return;
    long r = i / cols; int c = (int)(i % cols);
    dst[r * ldd + c] = src[r * lds + c];
}

// ======================= edge gather: max + stats =======================
__global__ void __launch_bounds__(256) k_edge(const float* __restrict__ PQ,
                                              const int* __restrict__ knn,
                                              float* __restrict__ mx,
                                              float* __restrict__ ssum,
                                              float* __restrict__ sssq,
                                              int Co)
{
    __shared__ long nbb[KNB];
    long bn = blockIdx.x;
    int  b  = (int)(bn / NP);
    if (threadIdx.x < KNB) {
        int nb = knn[bn * KNB + threadIdx.x];
        nbb[threadIdx.x] = ((long)b * NP + nb) * (2 * Co) + Co;
    }
    __syncthreads();
    const float* Prow = PQ + bn * (2 * Co);
    for (int o = threadIdx.x; o < Co; o += 256) {
        float p = Prow[o];
        float mv = -3.4e38f, s = 0.f, ss = 0.f;
        #pragma unroll
        for (int k2 = 0; k2 < KNB; k2++) {
            float v = p + PQ[nbb[k2] + o];
            mv = fmaxf(mv, v); s += v; ss += v * v;
        }
        mx[bn * Co + o] = mv;
        atomicAdd(&ssum[b * 1024 + o], s);
        atomicAdd(&sssq[b * 1024 + o], ss);
    }
}

// ======================= per-channel stats over N =======================
__global__ void __launch_bounds__(256) k_colsum(const float* __restrict__ X, int ldx,
                                                float* __restrict__ ssum,
                                                float* __restrict__ sssq, int Co)
{
    int nch = NP / 128;
    int b  = blockIdx.x / nch;
    int ch = blockIdx.x % nch;
    long r0 = (long)b * NP + ch * 128;
    for (int o = threadIdx.x; o < Co; o += 256) {
        float s = 0.f, ss = 0.f;
        for (int r = 0; r < 128; r++) {
            float v = X[(r0 + r) * ldx + o];
            s += v; ss += v * v;
        }
        atomicAdd(&ssum[b * 1024 + o], s);
        atomicAdd(&sssq[b * 1024 + o], ss);
    }
}

// ======================= normalize + activation =======================
__global__ void k_norm_act(const float* __restrict__ X, int ldx, int offx,
                           float* __restrict__ Y, int ldy, int offy,
                           const float* __restrict__ ssum,
                           const float* __restrict__ sssq,
                           int Co, float invcnt, int act)
{
    long i = blockIdx.x * (long)blockDim.x + threadIdx.x;
    long total = (long)BB * NP * Co;
    if (i >= total) return;
    int  o  = (int)(i % Co);
    long rn = i / Co;
    int  b  = (int)(rn / NP);
    float mu  = ssum[b * 1024 + o] * invcnt;
    float var = sssq[b * 1024 + o] * invcnt - mu * mu;
    float v = (X[rn * ldx + offx + o] - mu) * rsqrtf(var + EPSI);
    if (act == 1) v = (v >= 0.f) ? v : 0.2f * v;
    else          v = (v > 0.f)  ? v : 0.f;
    Y[rn * ldy + offy + o] = v;
}

// ======================= softmax -> bf16 hi/lo =======================
__global__ void __launch_bounds__(256) k_softmax_b(const float* __restrict__ S,
                                                   __nv_bfloat16* __restrict__ H,
                                                   __nv_bfloat16* __restrict__ L)
{
    __shared__ float row[2048];
    __shared__ float red[8];
    const float* rp = S + (long)blockIdx.x * 2048;
    __nv_bfloat16* hp = H + (long)blockIdx.x * 2048;
    __nv_bfloat16* lp = L + (long)blockIdx.x * 2048;
    int tid = threadIdx.x;
    float mx = -3.4e38f;
    for (int j = tid; j < 2048; j += 256) { float v = rp[j]; row[j] = v; mx = fmaxf(mx, v); }
    #pragma unroll
    for (int off = 16; off; off >>= 1) mx = fmaxf(mx, __shfl_xor_sync(0xffffffffu, mx, off));
    if ((tid & 31) == 0) red[tid >> 5] = mx;
    __syncthreads();
    mx = red[0];
    #pragma unroll
    for (int w = 1; w < 8; w++) mx = fmaxf(mx, red[w]);
    __syncthreads();
    float s = 0.f;
    for (int j = tid; j < 2048; j += 256) { float e = expf(row[j] - mx); row[j] = e; s += e; }
    #pragma unroll
    for (int off = 16; off; off >>= 1) s += __shfl_xor_sync(0xffffffffu, s, off);
    if ((tid & 31) == 0) red[tid >> 5] = s;
    __syncthreads();
    s = 0.f;
    #pragma unroll
    for (int w = 0; w < 8; w++) s += red[w];
    float inv = 1.f / s;
    for (int j = tid; j < 2048; j += 256) {
        float p = row[j] * inv;
        __nv_bfloat16 h, l;
        split2(p, h, l);
        hp[j] = h; lp[j] = l;
    }
}

// ======================= attention permutes (fp32 -> bf16 hi/lo) ==============
__global__ void k_perm_qk_b(const float* __restrict__ raw,
                            __nv_bfloat16* __restrict__ H, __nv_bfloat16* __restrict__ L)
{
    long i = blockIdx.x * (long)blockDim.x + threadIdx.x;
    if (i >= (long)BB * NP * 256) return;
    int c = (int)(i % 256); long bn = i / 256;
    int n = (int)(bn % NP); int b = (int)(bn / NP);
    int h = c & 3, dd = c >> 2;
    long oi = (((long)b * 4 + h) * NP + n) * 64 + dd;
    __nv_bfloat16 hi, lo;
    split2(raw[i], hi, lo);
    H[oi] = hi; L[oi] = lo;
}
__global__ void k_perm_v_b(const float* __restrict__ raw,
                           __nv_bfloat16* __restrict__ H, __nv_bfloat16* __restrict__ L)
{
    long i = blockIdx.x * (long)blockDim.x + threadIdx.x;
    if (i >= (long)BB * NP * 256) return;
    int c = (int)(i % 256); long bn = i / 256;
    int n = (int)(bn % NP); int b = (int)(bn / NP);
    int h = c & 3, dd = c >> 2;
    long oi = (((long)b * 4 + h) * 64 + dd) * NP + n;
    __nv_bfloat16 hi, lo;
    split2(raw[i], hi, lo);
    H[oi] = hi; L[oi] = lo;
}
__global__ void k_perm_o_b(const float* __restrict__ OH,
                           __nv_bfloat16* __restrict__ H, __nv_bfloat16* __restrict__ L)
{
    long i = blockIdx.x * (long)blockDim.x + threadIdx.x;
    if (i >= (long)BB * NP * 256) return;
    int c = (int)(i % 256); long bn = i / 256;
    int n = (int)(bn % NP); int b = (int)(bn / NP);
    int h = c & 3, dd = c >> 2;
    __nv_bfloat16 hi, lo;
    split2(OH[(((long)b * 4 + h) * NP + n) * 64 + dd], hi, lo);
    H[i] = hi; L[i] = lo;
}

// ======================= host orchestration =======================
#define SMEM128 (2 * 128 * 144 + 2 * 128 * 144)
#define SMEM64  (2 * 128 * 144 + 2 * 64 * 144)

static void tcg(const __nv_bfloat16* AH, const __nv_bfloat16* AL, long lda, long sA,
                const __nv_bfloat16* WH, const __nv_bfloat16* WL, long ldw, long sW,
                const float* bias, float alpha,
                float* C, int ldc, long sC, int M, int Nout, int K, int Z)
{
    if (Nout % 128 == 0) {
        dim3 g(Nout / 128, M / 128, Z);
        mma_gemm<128><<<g, 256, SMEM128>>>(AH, AL, lda, sA, WH, WL, ldw, sW,
                                           bias, alpha, C, ldc, sC, K);
    } else {
        dim3 g(Nout / 64, M / 128, Z);
        mma_gemm<64><<<g, 256, SMEM64>>>(AH, AL, lda, sA, WH, WL, ldw, sW,
                                         bias, alpha, C, ldc, sC, K);
    }
}

extern "C" void kernel_launch(void* const* d_in, const int* in_sizes, int n_in,
                              void* d_out, int out_size)
{
    const float* coords1 = (const float*)d_in[0];
    const float* feats1  = (const float*)d_in[1];
    const float* coords2 = (const float*)d_in[2];
    const float* feats2  = (const float*)d_in[3];
    const float* gW1 = (const float*)d_in[4];
    const float* gW2 = (const float*)d_in[5];
    const float* gW3 = (const float*)d_in[6];
    const float* Wq  = (const float*)d_in[7];  const float* bq  = (const float*)d_in[8];
    const float* Wk  = (const float*)d_in[9];  const float* bk  = (const float*)d_in[10];
    const float* Wv  = (const float*)d_in[11]; const float* bv  = (const float*)d_in[12];
    const float* Wo  = (const float*)d_in[13]; const float* bo  = (const float*)d_in[14];
    const float* Wm1 = (const float*)d_in[15]; const float* bm1 = (const float*)d_in[16];
    const float* Wm2 = (const float*)d_in[17]; const float* bm2 = (const float*)d_in[18];
    float* out = (float*)d_out;

    static int smem_set = 0;
    if (!smem_set) {
        cudaFuncSetAttribute(mma_gemm<128>, cudaFuncAttributeMaxDynamicSharedMemorySize, SMEM128);
        cudaFuncSetAttribute(mma_gemm<64>,  cudaFuncAttributeMaxDynamicSharedMemorySize, SMEM64);
        smem_set = 1;
    }

    void* pv;
    float *FE[2]; int *KN[2];
    cudaGetSymbolAddress(&pv, d_FE0); FE[0] = (float*)pv;
    cudaGetSymbolAddress(&pv, d_FE1); FE[1] = (float*)pv;
    cudaGetSymbolAddress(&pv, d_KN0); KN[0] = (int*)pv;
    cudaGetSymbolAddress(&pv, d_KN1); KN[1] = (int*)pv;
    cudaGetSymbolAddress(&pv, d_CC);  float* CCp = (float*)pv;
    cudaGetSymbolAddress(&pv, d_PQ);  float* PQp = (float*)pv;
    cudaGetSymbolAddress(&pv, d_MX);  float* MXp = (float*)pv;
    cudaGetSymbolAddress(&pv, d_SC);  float* SCp = (float*)pv;
    cudaGetSymbolAddress(&pv, d_OH);  float* OHp = (float*)pv;
    cudaGetSymbolAddress(&pv, d_STT); float* STp = (float*)pv;
    __nv_bfloat16 *AH, *AL, *WH, *WL, *QHH, *QHL, *KHH, *KHL, *VTH, *VTL, *SCH, *SCL;
    cudaGetSymbolAddress(&pv, d_AH);  AH  = (__nv_bfloat16*)pv;
    cudaGetSymbolAddress(&pv, d_AL);  AL  = (__nv_bfloat16*)pv;
    cudaGetSymbolAddress(&pv, d_WH);  WH  = (__nv_bfloat16*)pv;
    cudaGetSymbolAddress(&pv, d_WL);  WL  = (__nv_bfloat16*)pv;
    cudaGetSymbolAddress(&pv, d_QHH); QHH = (__nv_bfloat16*)pv;
    cudaGetSymbolAddress(&pv, d_QHL); QHL = (__nv_bfloat16*)pv;
    cudaGetSymbolAddress(&pv, d_KHH); KHH = (__nv_bfloat16*)pv;
    cudaGetSymbolAddress(&pv, d_KHL); KHL = (__nv_bfloat16*)pv;
    cudaGetSymbolAddress(&pv, d_VTH); VTH = (__nv_bfloat16*)pv;
    cudaGetSymbolAddress(&pv, d_VTL); VTL = (__nv_bfloat16*)pv;
    cudaGetSymbolAddress(&pv, d_SCH); SCH = (__nv_bfloat16*)pv;
    cudaGetSymbolAddress(&pv, d_SCL); SCL = (__nv_bfloat16*)pv;
    float* SUM = STp;
    float* SSQ = STp + BB * 1024;

    const long M4  = (long)BB * NP;  // 4096
    const int  EWB = 256;
    dim3 tb(32, 8);

    k_transpose<<<dim3(NP / 32, 256 / 32, BB), tb>>>(feats1, FE[0], 256, NP);
    k_transpose<<<dim3(NP / 32, 256 / 32, BB), tb>>>(feats2, FE[1], 256, NP);
    k_knn<<<BB * NP, 256>>>(coords1, KN[0]);
    k_knn<<<BB * NP, 256>>>(coords2, KN[1]);

    for (int li = 0; li < 4; li++) {
        int i = li / 2;
        if ((li & 1) == 0) {
            // ---------------- GCN layer i ----------------
            for (int cl = 0; cl < 2; cl++) {
                long tot = M4 * 256;
                k_copy<<<(tot + EWB - 1) / EWB, EWB>>>(FE[cl], 256, CCp, 1024, M4, 256);
                // sublayer 1
                k_cvt<<<(M4 * 256 / 4 + 255) / 256, 256>>>(FE[cl], 256, 256, M4 * 256, AH, AL);
                k_prepw_b<<<(256 * 256 + 255) / 256, 256>>>(gW1 + (long)i * 256 * 512, WH, WL, 256, 256);
                tcg(AH, AL, 256, 0, WH, WL, 256, 0, nullptr, 1.f, PQp, 512, 0, (int)M4, 512, 256, 1);
                cudaMemsetAsync(STp, 0, sizeof(float) * 2 * BB * 1024, 0);
                k_edge<<<BB * NP, 256>>>(PQp, KN[cl], MXp, SUM, SSQ, 256);
                k_norm_act<<<(M4 * 256 + EWB - 1) / EWB, EWB>>>(MXp, 256, 0, CCp, 1024, 256,
                                                                SUM, SSQ, 256, 1.f / 32768.f, 1);
                // sublayer 2
                k_cvt<<<(M4 * 256 / 4 + 255) / 256, 256>>>(CCp + 256, 1024, 256, M4 * 256, AH, AL);
                k_prepw_b<<<(512 * 256 + 255) / 256, 256>>>(gW2 + (long)i * 512 * 512, WH, WL, 512, 256);
                tcg(AH, AL, 256, 0, WH, WL, 256, 0, nullptr, 1.f, PQp, 1024, 0, (int)M4, 1024, 256, 1);
                cudaMemsetAsync(STp, 0, sizeof(float) * 2 * BB * 1024, 0);
                k_edge<<<BB * NP, 256>>>(PQp, KN[cl], MXp, SUM, SSQ, 512);
                k_norm_act<<<(M4 * 512 + EWB - 1) / EWB, EWB>>>(MXp, 512, 0, CCp, 1024, 512,
                                                                SUM, SSQ, 512, 1.f / 32768.f, 1);
                // W3 on concat
                k_cvt<<<(M4 * 1024 / 4 + 255) / 256, 256>>>(CCp, 1024, 1024, M4 * 1024, AH, AL);
                k_cvt<<<(256 * 1024 / 4 + 255) / 256, 256>>>(gW3 + (long)i * 256 * 1024, 1024, 1024,
                                                             256 * 1024, WH, WL);
                tcg(AH, AL, 1024, 0, WH, WL, 1024, 0, nullptr, 1.f, MXp, 256, 0, (int)M4, 256, 1024, 1);
                cudaMemsetAsync(STp, 0, sizeof(float) * 2 * BB * 1024, 0);
                k_colsum<<<BB * (NP / 128), 256>>>(MXp, 256, SUM, SSQ, 256);
                k_norm_act<<<(M4 * 256 + EWB - 1) / EWB, EWB>>>(MXp, 256, 0, FE[cl], 256, 0,
                                                                SUM, SSQ, 256, 1.f / (float)NP, 1);
            }
        } else {
            // ---------------- cross-attention layer i ----------------
            for (int a = 0; a < 2; a++) {
                const float* f1p = FE[a];
                const float* f2p = FE[1 - a];
                long tot = M4 * 256;
                // Q projection (A = f1)
                k_cvt<<<(tot / 4 + 255) / 256, 256>>>(f1p, 256, 256, tot, AH, AL);
                k_cvt<<<(65536 / 4 + 255) / 256, 256>>>(Wq + (long)i * 65536, 256, 256, 65536, WH, WL);
                tcg(AH, AL, 256, 0, WH, WL, 256, 0, bq + (long)i * 256, 1.f, MXp, 256, 0, (int)M4, 256, 256, 1);
                k_perm_qk_b<<<(tot + EWB - 1) / EWB, EWB>>>(MXp, QHH, QHL);
                // K / V projections (A = f2)
                k_cvt<<<(tot / 4 + 255) / 256, 256>>>(f2p, 256, 256, tot, AH, AL);
                k_cvt<<<(65536 / 4 + 255) / 256, 256>>>(Wk + (long)i * 65536, 256, 256, 65536, WH, WL);
                tcg(AH, AL, 256, 0, WH, WL, 256, 0, bk + (long)i * 256, 1.f, MXp, 256, 0, (int)M4, 256, 256, 1);
                k_perm_qk_b<<<(tot + EWB - 1) / EWB, EWB>>>(MXp, KHH, KHL);
                k_cvt<<<(65536 / 4 + 255) / 256, 256>>>(Wv + (long)i * 65536, 256, 256, 65536, WH, WL);
                tcg(AH, AL, 256, 0, WH, WL, 256, 0, bv + (long)i * 256, 1.f, MXp, 256, 0, (int)M4, 256, 256, 1);
                k_perm_v_b<<<(tot + EWB - 1) / EWB, EWB>>>(MXp, VTH, VTL);
                // scores = Q K^T / 8
                tcg(QHH, QHL, 64, (long)NP * 64, KHH, KHL, 64, (long)NP * 64, nullptr, 0.125f,
                    SCp, 2048, (long)2048 * 2048, 2048, 2048, 64, 8);
                k_softmax_b<<<8 * 2048, 256>>>(SCp, SCH, SCL);
                // O = attn @ V
                tcg(SCH, SCL, 2048, (long)2048 * 2048, VTH, VTL, 2048, (long)64 * NP, nullptr, 1.f,
                    OHp, 64, (long)NP * 64, 2048, 64, 2048, 8);
                k_perm_o_b<<<(tot + EWB - 1) / EWB, EWB>>>(OHp, AH, AL);
                // concat [f1, Wo(attn)+bo] -> CC (512 wide)
                k_copy<<<(tot + EWB - 1) / EWB, EWB>>>(f1p, 256, CCp, 512, M4, 256);
                k_cvt<<<(65536 / 4 + 255) / 256, 256>>>(Wo + (long)i * 65536, 256, 256, 65536, WH, WL);
                tcg(AH, AL, 256, 0, WH, WL, 256, 0, bo + (long)i * 256, 1.f, CCp + 256, 512, 0, (int)M4, 256, 256, 1);
                // Wm1 -> inorm -> relu -> Wm2
                k_cvt<<<(M4 * 512 / 4 + 255) / 256, 256>>>(CCp, 512, 512, M4 * 512, AH, AL);
                k_cvt<<<(262144 / 4 + 255) / 256, 256>>>(Wm1 + (long)i * 262144, 512, 512, 262144, WH, WL);
                tcg(AH, AL, 512, 0, WH, WL, 512, 0, bm1 + (long)i * 512, 1.f, PQp, 512, 0, (int)M4, 512, 512, 1);
                cudaMemsetAsync(STp, 0, sizeof(float) * 2 * BB * 1024, 0);
                k_colsum<<<BB * (NP / 128), 256>>>(PQp, 512, SUM, SSQ, 512);
                k_norm_act<<<(M4 * 512 + EWB - 1) / EWB, EWB>>>(PQp, 512, 0, PQp, 512, 0,
                                                                SUM, SSQ, 512, 1.f / (float)NP, 2);
                k_cvt<<<(M4 * 512 / 4 + 255) / 256, 256>>>(PQp, 512, 512, M4 * 512, AH, AL);
                k_cvt<<<(131072 / 4 + 255) / 256, 256>>>(Wm2 + (long)i * 131072, 512, 512, 131072, WH, WL);
                tcg(AH, AL, 512, 0, WH, WL, 512, 0, bm2 + (long)i * 256, 1.f, FE[a], 256, 0, (int)M4, 256, 512, 1);
            }
        }
    }

    k_transpose<<<dim3(256 / 32, NP / 32, BB), tb>>>(FE[0], out, NP, 256);
    k_transpose<<<dim3(256 / 32, NP / 32, BB), tb>>>(FE[1], out + (long)BB * 256 * NP, NP, 256);
}

// round 4
// speedup vs baseline: 1.9865x; 1.4200x over previous
#include <cuda_runtime.h>
#include <cuda_bf16.h>
#include <cstdint>

#define BB   2
#define NP   2048
#define KNB  16
#define EPSI 1e-5f
#define M4   (BB*NP)        // 4096
#define M8   (2*BB*NP)      // 8192

// ======================= helpers =======================
__device__ __forceinline__ void split2(float x, __nv_bfloat16& h, __nv_bfloat16& l){
    h = __float2bfloat16(x);
    l = __float2bfloat16(x - __bfloat162float(h));
}
__device__ __forceinline__ uint32_t packbf(__nv_bfloat16 a, __nv_bfloat16 b){
    return ((uint32_t)__bfloat16_as_ushort(b) << 16) | (uint32_t)__bfloat16_as_ushort(a);
}

#define MMA16816(d, a, b) \
    asm volatile("mma.sync.aligned.m16n8k16.row.col.f32.bf16.bf16.f32 " \
        "{%0,%1,%2,%3}, {%4,%5,%6,%7}, {%8,%9}, {%0,%1,%2,%3};" \
        : "+f"((d)[0]), "+f"((d)[1]), "+f"((d)[2]), "+f"((d)[3]) \
        : "r"((a)[0]), "r"((a)[1]), "r"((a)[2]), "r"((a)[3]), \
          "r"((b)[0]), "r"((b)[1]))

// ======================= device scratch =======================
__device__ __align__(16) float d_FE [M8*256];      // both clouds contiguous
__device__ int   d_KN [M8*KNB];
__device__ __align__(16) float d_CC [M8*1024];
__device__ __align__(16) float d_PQ [M8*1024];
__device__ __align__(16) float d_MX [M8*512];
__device__ __align__(16) float d_OH [BB*4*NP*64];
__device__ float d_STT[2*4*1024];
__device__ __align__(16) __nv_bfloat16 d_AH [M8*1024];
__device__ __align__(16) __nv_bfloat16 d_AL [M8*1024];
__device__ __align__(16) __nv_bfloat16 d_WH [1024*256];
__device__ __align__(16) __nv_bfloat16 d_WL [1024*256];
__device__ __align__(16) __nv_bfloat16 d_WQH[256*256],  d_WQL[256*256];
__device__ __align__(16) __nv_bfloat16 d_WKH[256*256],  d_WKL[256*256];
__device__ __align__(16) __nv_bfloat16 d_WVH[256*256],  d_WVL[256*256];
__device__ __align__(16) __nv_bfloat16 d_WOH[256*256],  d_WOL[256*256];
__device__ __align__(16) __nv_bfloat16 d_WM1H[512*512], d_WM1L[512*512];
__device__ __align__(16) __nv_bfloat16 d_WM2H[256*512], d_WM2L[256*512];
__device__ __align__(16) __nv_bfloat16 d_QHH[BB*4*NP*64], d_QHL[BB*4*NP*64];
__device__ __align__(16) __nv_bfloat16 d_KHH[BB*4*NP*64], d_KHL[BB*4*NP*64];
__device__ __align__(16) __nv_bfloat16 d_VTH[BB*4*64*NP], d_VTL[BB*4*64*NP];

// ======================= transpose =======================
__global__ void k_transpose(const float* __restrict__ in, float* __restrict__ out,
                            int R, int Cc)
{
    __shared__ float t[32][33];
    int b  = blockIdx.z;
    const float* ip = in  + (long)b * R * Cc;
    float*       op = out + (long)b * R * Cc;
    int c0 = blockIdx.x * 32, r0 = blockIdx.y * 32;
    for (int i = threadIdx.y; i < 32; i += 8)
        t[i][threadIdx.x] = ip[(long)(r0 + i) * Cc + c0 + threadIdx.x];
    __syncthreads();
    for (int i = threadIdx.y; i < 32; i += 8)
        op[(long)(c0 + i) * R + r0 + threadIdx.x] = t[threadIdx.x][i];
}

// ======================= kNN =======================
__global__ void __launch_bounds__(256) k_knn(const float* __restrict__ coords,
                                             int* __restrict__ knn)
{
    __shared__ float sx[NP], sy[NP], sz[NP], sd[NP];
    __shared__ float wv[8];
    __shared__ int   wi[8];
    int b = blockIdx.x / NP;
    int n = blockIdx.x % NP;
    const float* cb = coords + (long)b * 3 * NP;
    for (int j = threadIdx.x; j < NP; j += 256) {
        sx[j] = cb[j]; sy[j] = cb[NP + j]; sz[j] = cb[2 * NP + j];
    }
    __syncthreads();
    float xn = sx[n], yn = sy[n], zn = sz[n];
    float sqn = xn*xn + yn*yn + zn*zn;
    for (int j = threadIdx.x; j < NP; j += 256) {
        float x = sx[j], y = sy[j], z = sz[j];
        float d = sqn + (x*x + y*y + z*z) - 2.f * (xn*x + yn*y + zn*z);
        sd[j] = (j == n) ? 3.4e38f : d;
    }
    __syncthreads();
    int lane = threadIdx.x & 31, warp = threadIdx.x >> 5;
    for (int r = 0; r < KNB; r++) {
        float best = 3.0e38f; int bi = NP;
        for (int j = threadIdx.x; j < NP; j += 256) {
            float v = sd[j];
            if (v < best) { best = v; bi = j; }
        }
        #pragma unroll
        for (int off = 16; off; off >>= 1) {
            float ov = __shfl_down_sync(0xffffffffu, best, off);
            int   oi = __shfl_down_sync(0xffffffffu, bi,   off);
            if (ov < best || (ov == best && oi < bi)) { best = ov; bi = oi; }
        }
        if (lane == 0) { wv[warp] = best; wi[warp] = bi; }
        __syncthreads();
        if (threadIdx.x == 0) {
            float fb = wv[0]; int fi = wi[0];
            for (int w = 1; w < 8; w++)
                if (wv[w] < fb || (wv[w] == fb && wi[w] < fi)) { fb = wv[w]; fi = wi[w]; }
            knn[((long)b * NP + n) * KNB + r] = fi;
            sd[fi] = 3.4e38f;
        }
        __syncthreads();
    }
}

// ======================= HMMA GEMM (bf16 hi/lo 3-pass) =======================
template <int BN>
__global__ void __launch_bounds__(256) mma_gemm(
    const __nv_bfloat16* __restrict__ AH, const __nv_bfloat16* __restrict__ AL,
    long lda, long sA,
    const __nv_bfloat16* __restrict__ WH, const __nv_bfloat16* __restrict__ WL,
    long ldw, long sW,
    const float* __restrict__ bias, float alpha,
    float* __restrict__ C, int ldc, long sC, int K)
{
    constexpr int MT = (BN == 128) ? 4 : 2;
    constexpr int NT = 4;
    extern __shared__ __align__(16) char smem[];
    char* sAh = smem;
    char* sAl = smem + 128 * 144;
    char* sWh = smem + 2 * 128 * 144;
    char* sWl = smem + 2 * 128 * 144 + BN * 144;

    int tid = threadIdx.x, wid = tid >> 5, lane = tid & 31;
    int g = lane >> 2, tg = lane & 3;
    int wm = (BN == 128) ? (wid >> 2) * 64 : (wid >> 1) * 32;
    int wn = (BN == 128) ? (wid & 3) * 32 : (wid & 1) * 32;

    long m0 = (long)blockIdx.y * 128;
    int  n0 = blockIdx.x * BN;
    int  z  = blockIdx.z;
    const __nv_bfloat16* pAH = AH + (long)z * sA + m0 * lda;
    const __nv_bfloat16* pAL = AL + (long)z * sA + m0 * lda;
    const __nv_bfloat16* pWH = WH + (long)z * sW + (long)n0 * ldw;
    const __nv_bfloat16* pWL = WL + (long)z * sW + (long)n0 * ldw;

    float acc[MT][NT][4];
    #pragma unroll
    for (int mt = 0; mt < MT; mt++)
        #pragma unroll
        for (int nt = 0; nt < NT; nt++)
            #pragma unroll
            for (int q = 0; q < 4; q++) acc[mt][nt][q] = 0.f;

    for (int k0 = 0; k0 < K; k0 += 64) {
        #pragma unroll
        for (int it = 0; it < 4; it++) {
            int i = tid + it * 256;
            int r = i >> 3, q = i & 7;
            *(uint4*)(sAh + r * 144 + q * 16) = *(const uint4*)(pAH + (long)r * lda + k0 + q * 8);
            *(uint4*)(sAl + r * 144 + q * 16) = *(const uint4*)(pAL + (long)r * lda + k0 + q * 8);
        }
        #pragma unroll
        for (int i = tid; i < BN * 8; i += 256) {
            int r = i >> 3, q = i & 7;
            *(uint4*)(sWh + r * 144 + q * 16) = *(const uint4*)(pWH + (long)r * ldw + k0 + q * 8);
            *(uint4*)(sWl + r * 144 + q * 16) = *(const uint4*)(pWL + (long)r * ldw + k0 + q * 8);
        }
        __syncthreads();

        #pragma unroll
        for (int ks = 0; ks < 4; ks++) {
            int kb = ks * 16;
            uint32_t ah[MT][4], al[MT][4];
            #pragma unroll
            for (int mt = 0; mt < MT; mt++) {
                int roff = (wm + mt * 16 + g) * 144 + (kb + tg * 2) * 2;
                ah[mt][0] = *(const uint32_t*)(sAh + roff);
                ah[mt][1] = *(const uint32_t*)(sAh + roff + 8 * 144);
                ah[mt][2] = *(const uint32_t*)(sAh + roff + 16);
                ah[mt][3] = *(const uint32_t*)(sAh + roff + 8 * 144 + 16);
                al[mt][0] = *(const uint32_t*)(sAl + roff);
                al[mt][1] = *(const uint32_t*)(sAl + roff + 8 * 144);
                al[mt][2] = *(const uint32_t*)(sAl + roff + 16);
                al[mt][3] = *(const uint32_t*)(sAl + roff + 8 * 144 + 16);
            }
            uint32_t bh[NT][2], bl[NT][2];
            #pragma unroll
            for (int nt = 0; nt < NT; nt++) {
                int roff = (wn + nt * 8 + g) * 144 + (kb + tg * 2) * 2;
                bh[nt][0] = *(const uint32_t*)(sWh + roff);
                bh[nt][1] = *(const uint32_t*)(sWh + roff + 16);
                bl[nt][0] = *(const uint32_t*)(sWl + roff);
                bl[nt][1] = *(const uint32_t*)(sWl + roff + 16);
            }
            #pragma unroll
            for (int mt = 0; mt < MT; mt++)
                #pragma unroll
                for (int nt = 0; nt < NT; nt++) {
                    MMA16816(acc[mt][nt], ah[mt], bh[nt]);
                    MMA16816(acc[mt][nt], ah[mt], bl[nt]);
                    MMA16816(acc[mt][nt], al[mt], bh[nt]);
                }
        }
        __syncthreads();
    }

    float* Cz = C + (long)z * sC;
    #pragma unroll
    for (int mt = 0; mt < MT; mt++) {
        long row = m0 + wm + mt * 16 + g;
        #pragma unroll
        for (int nt = 0; nt < NT; nt++) {
            int col = n0 + wn + nt * 8 + tg * 2;
            float b0 = 0.f, b1 = 0.f;
            if (bias) { b0 = __ldg(&bias[col]); b1 = __ldg(&bias[col + 1]); }
            float2 v0, v1;
            v0.x = acc[mt][nt][0] * alpha + b0;
            v0.y = acc[mt][nt][1] * alpha + b1;
            v1.x = acc[mt][nt][2] * alpha + b0;
            v1.y = acc[mt][nt][3] * alpha + b1;
            *(float2*)(Cz + row * (long)ldc + col)       = v0;
            *(float2*)(Cz + (row + 8) * (long)ldc + col) = v1;
        }
    }
}

// ======================= fused flash attention =======================
// grid (16 qblocks, 8 z), 256 threads. Q/K: (z,n,64) bf16 hi/lo; V: (z,d,m).
// O: (z,n,64) fp32. Scores pre-scaled via Q (0.125 folded into Q split).
#define FA_SMEM (2*128*144 + 4*64*144)
__global__ void __launch_bounds__(256) k_flash(
    const __nv_bfloat16* __restrict__ QH, const __nv_bfloat16* __restrict__ QL,
    const __nv_bfloat16* __restrict__ KH, const __nv_bfloat16* __restrict__ KL,
    const __nv_bfloat16* __restrict__ VH, const __nv_bfloat16* __restrict__ VL,
    float* __restrict__ O)
{
    extern __shared__ __align__(16) char smem[];
    char* sQh = smem;
    char* sQl = smem + 128*144;
    char* sKh = smem + 2*128*144;
    char* sKl = sKh + 64*144;
    char* sVh = sKl + 64*144;
    char* sVl = sVh + 64*144;

    int tid = threadIdx.x, wid = tid >> 5, lane = tid & 31;
    int g = lane >> 2, tg = lane & 3;
    int z = blockIdx.y;
    long q0 = (long)blockIdx.x * 128;
    int wm = wid * 16;

    const __nv_bfloat16* pQH = QH + ((long)z * NP + q0) * 64;
    const __nv_bfloat16* pQL = QL + ((long)z * NP + q0) * 64;

    #pragma unroll
    for (int it = 0; it < 4; it++) {
        int i = tid + it * 256;
        int r = i >> 3, q = i & 7;
        *(uint4*)(sQh + r * 144 + q * 16) = *(const uint4*)(pQH + r * 64 + q * 8);
        *(uint4*)(sQl + r * 144 + q * 16) = *(const uint4*)(pQL + r * 64 + q * 8);
    }

    float m0 = -3.4e38f, m1 = -3.4e38f, l0 = 0.f, l1 = 0.f;
    float acc[8][4];
    #pragma unroll
    for (int nt = 0; nt < 8; nt++)
        #pragma unroll
        for (int q = 0; q < 4; q++) acc[nt][q] = 0.f;

    for (int c = 0; c < NP / 64; c++) {
        const __nv_bfloat16* pKH = KH + ((long)z * NP + c * 64) * 64;
        const __nv_bfloat16* pKL = KL + ((long)z * NP + c * 64) * 64;
        const __nv_bfloat16* pVH = VH + (long)z * 64 * NP + c * 64;
        const __nv_bfloat16* pVL = VL + (long)z * 64 * NP + c * 64;
        #pragma unroll
        for (int it = 0; it < 2; it++) {
            int i = tid + it * 256;
            int r = i >> 3, q = i & 7;
            *(uint4*)(sKh + r * 144 + q * 16) = *(const uint4*)(pKH + r * 64 + q * 8);
            *(uint4*)(sKl + r * 144 + q * 16) = *(const uint4*)(pKL + r * 64 + q * 8);
            *(uint4*)(sVh + r * 144 + q * 16) = *(const uint4*)(pVH + (long)r * NP + q * 8);
            *(uint4*)(sVl + r * 144 + q * 16) = *(const uint4*)(pVL + (long)r * NP + q * 8);
        }
        __syncthreads();

        // S = Q K^T  (warp: 16 rows x 64 keys)
        float sacc[8][4];
        #pragma unroll
        for (int nt = 0; nt < 8; nt++)
            #pragma unroll
            for (int q = 0; q < 4; q++) sacc[nt][q] = 0.f;
        #pragma unroll
        for (int kk = 0; kk < 4; kk++) {
            int kb = kk * 16;
            uint32_t aqh[4], aql[4];
            int roff = (wm + g) * 144 + (kb + tg * 2) * 2;
            aqh[0] = *(const uint32_t*)(sQh + roff);
            aqh[1] = *(const uint32_t*)(sQh + roff + 8 * 144);
            aqh[2] = *(const uint32_t*)(sQh + roff + 16);
            aqh[3] = *(const uint32_t*)(sQh + roff + 8 * 144 + 16);
            aql[0] = *(const uint32_t*)(sQl + roff);
            aql[1] = *(const uint32_t*)(sQl + roff + 8 * 144);
            aql[2] = *(const uint32_t*)(sQl + roff + 16);
            aql[3] = *(const uint32_t*)(sQl + roff + 8 * 144 + 16);
            #pragma unroll
            for (int nt = 0; nt < 8; nt++) {
                uint32_t bh[2], bl[2];
                int boff = (nt * 8 + g) * 144 + (kb + tg * 2) * 2;
                bh[0] = *(const uint32_t*)(sKh + boff);
                bh[1] = *(const uint32_t*)(sKh + boff + 16);
                bl[0] = *(const uint32_t*)(sKl + boff);
                bl[1] = *(const uint32_t*)(sKl + boff + 16);
                MMA16816(sacc[nt], aqh, bh);
                MMA16816(sacc[nt], aqh, bl);
                MMA16816(sacc[nt], aql, bh);
            }
        }

        // online softmax
        float rmax0 = -3.4e38f, rmax1 = -3.4e38f;
        #pragma unroll
        for (int nt = 0; nt < 8; nt++) {
            rmax0 = fmaxf(rmax0, fmaxf(sacc[nt][0], sacc[nt][1]));
            rmax1 = fmaxf(rmax1, fmaxf(sacc[nt][2], sacc[nt][3]));
        }
        rmax0 = fmaxf(rmax0, __shfl_xor_sync(0xffffffffu, rmax0, 1));
        rmax0 = fmaxf(rmax0, __shfl_xor_sync(0xffffffffu, rmax0, 2));
        rmax1 = fmaxf(rmax1, __shfl_xor_sync(0xffffffffu, rmax1, 1));
        rmax1 = fmaxf(rmax1, __shfl_xor_sync(0xffffffffu, rmax1, 2));
        float mn0 = fmaxf(m0, rmax0), mn1 = fmaxf(m1, rmax1);
        float al0 = __expf(m0 - mn0), al1 = __expf(m1 - mn1);
        m0 = mn0; m1 = mn1;

        float rs0 = 0.f, rs1 = 0.f;
        uint32_t pfh[4][4], pfl[4][4];
        #pragma unroll
        for (int nt = 0; nt < 8; nt++) {
            float p0 = __expf(sacc[nt][0] - mn0);
            float p1 = __expf(sacc[nt][1] - mn0);
            float p2 = __expf(sacc[nt][2] - mn1);
            float p3 = __expf(sacc[nt][3] - mn1);
            rs0 += p0 + p1; rs1 += p2 + p3;
            __nv_bfloat16 h0,lo0,h1,lo1,h2,lo2,h3,lo3;
            split2(p0,h0,lo0); split2(p1,h1,lo1); split2(p2,h2,lo2); split2(p3,h3,lo3);
            int kk = nt >> 1, base = (nt & 1) * 2;
            pfh[kk][base]     = packbf(h0, h1);
            pfh[kk][base + 1] = packbf(h2, h3);
            pfl[kk][base]     = packbf(lo0, lo1);
            pfl[kk][base + 1] = packbf(lo2, lo3);
        }
        rs0 += __shfl_xor_sync(0xffffffffu, rs0, 1);
        rs0 += __shfl_xor_sync(0xffffffffu, rs0, 2);
        rs1 += __shfl_xor_sync(0xffffffffu, rs1, 1);
        rs1 += __shfl_xor_sync(0xffffffffu, rs1, 2);
        l0 = l0 * al0 + rs0; l1 = l1 * al1 + rs1;
        #pragma unroll
        for (int nt = 0; nt < 8; nt++) {
            acc[nt][0] *= al0; acc[nt][1] *= al0;
            acc[nt][2] *= al1; acc[nt][3] *= al1;
        }

        // O += P V   (V as B frag: B[n=d][k=key])
        #pragma unroll
        for (int kk = 0; kk < 4; kk++) {
            #pragma unroll
            for (int nt = 0; nt < 8; nt++) {
                uint32_t bh[2], bl[2];
                int boff = (nt * 8 + g) * 144 + (kk * 16 + tg * 2) * 2;
                bh[0] = *(const uint32_t*)(sVh + boff);
                bh[1] = *(const uint32_t*)(sVh + boff + 16);
                bl[0] = *(const uint32_t*)(sVl + boff);
                bl[1] = *(const uint32_t*)(sVl + boff + 16);
                MMA16816(acc[nt], pfh[kk], bh);
                MMA16816(acc[nt], pfh[kk], bl);
                MMA16816(acc[nt], pfl[kk], bh);
            }
        }
        __syncthreads();
    }

    float inv0 = 1.f / l0, inv1 = 1.f / l1;
    float* pO = O + ((long)z * NP + q0 + wm) * 64;
    #pragma unroll
    for (int nt = 0; nt < 8; nt++) {
        int col = nt * 8 + tg * 2;
        float2 v0 = { acc[nt][0] * inv0, acc[nt][1] * inv0 };
        float2 v1 = { acc[nt][2] * inv1, acc[nt][3] * inv1 };
        *(float2*)(pO + (long)g * 64 + col)       = v0;
        *(float2*)(pO + (long)(g + 8) * 64 + col) = v1;
    }
}

// ======================= fp32 -> bf16 hi/lo split =======================
__global__ void k_cvt(const float* __restrict__ src, long lda, int K, long total,
                      __nv_bfloat16* __restrict__ H, __nv_bfloat16* __restrict__ L)
{
    long i = ((long)blockIdx.x * blockDim.x + threadIdx.x) * 4;
    if (i >= total) return;
    long r = i / K; int c = (int)(i - r * K);
    float4 v = *(const float4*)(src + r * lda + c);
    __nv_bfloat16 h0,h1,h2,h3,l0,l1,l2,l3;
    split2(v.x,h0,l0); split2(v.y,h1,l1); split2(v.z,h2,l2); split2(v.w,h3,l3);
    *(uint2*)(H + i) = make_uint2(packbf(h0,h1), packbf(h2,h3));
    *(uint2*)(L + i) = make_uint2(packbf(l0,l1), packbf(l2,l3));
}

__global__ void k_prepw_b(const float* __restrict__ W,
                          __nv_bfloat16* __restrict__ H, __nv_bfloat16* __restrict__ L,
                          int O, int Ci)
{
    long i = blockIdx.x * (long)blockDim.x + threadIdx.x;
    if (i >= (long)O * Ci) return;
    int o = (int)(i / Ci), c = (int)(i % Ci);
    float a  = W[(long)o * 2 * Ci + c];
    float bq = W[(long)o * 2 * Ci + Ci + c];
    __nv_bfloat16 h, l;
    split2(a - bq, h, l);
    H[(long)o * Ci + c] = h; L[(long)o * Ci + c] = l;
    split2(bq, h, l);
    H[((long)O + o) * Ci + c] = h; L[((long)O + o) * Ci + c] = l;
}

__global__ void k_copy(const float* __restrict__ src, int lds,
                       float* __restrict__ dst, int ldd, long rows, int cols)
{
    long i = blockIdx.x * (long)blockDim.x + threadIdx.x;
    if (i >= rows * (long)cols) return;
    long r = i / cols; int c = (int)(i % cols);
    dst[r * ldd + c] = src[r * lds + c];
}

// ======================= edge gather: max + stats =======================
__global__ void __launch_bounds__(256) k_edge(const float* __restrict__ PQ,
                                              const int* __restrict__ knn,
                                              float* __restrict__ mx,
                                              float* __restrict__ ssum,
                                              float* __restrict__ sssq,
                                              int Co)
{
    __shared__ long nbb[KNB];
    long bn = blockIdx.x;
    int  inst = (int)(bn / NP);
    if (threadIdx.x < KNB) {
        int nb = knn[bn * KNB + threadIdx.x];
        nbb[threadIdx.x] = ((long)inst * NP + nb) * (2 * Co) + Co;
    }
    __syncthreads();
    const float* Prow = PQ + bn * (2 * Co);
    for (int o = threadIdx.x; o < Co; o += 256) {
        float p = Prow[o];
        float mv = -3.4e38f, s = 0.f, ss = 0.f;
        #pragma unroll
        for (int k2 = 0; k2 < KNB; k2++) {
            float v = p + PQ[nbb[k2] + o];
            mv = fmaxf(mv, v); s += v; ss += v * v;
        }
        mx[bn * Co + o] = mv;
        atomicAdd(&ssum[inst * 1024 + o], s);
        atomicAdd(&sssq[inst * 1024 + o], ss);
    }
}

// ======================= per-channel stats over N =======================
__global__ void __launch_bounds__(256) k_colsum(const float* __restrict__ X, int ldx,
                                                float* __restrict__ ssum,
                                                float* __restrict__ sssq, int Co)
{
    int nch = NP / 128;
    int inst = blockIdx.x / nch;
    int ch   = blockIdx.x % nch;
    long r0 = (long)inst * NP + ch * 128;
    for (int o = threadIdx.x; o < Co; o += 256) {
        float s = 0.f, ss = 0.f;
        for (int r = 0; r < 128; r++) {
            float v = X[(r0 + r) * ldx + o];
            s += v; ss += v * v;
        }
        atomicAdd(&ssum[inst * 1024 + o], s);
        atomicAdd(&sssq[inst * 1024 + o], ss);
    }
}

// ======================= normalize + activation =======================
__global__ void k_norm_act(const float* __restrict__ X, int ldx, int offx,
                           float* __restrict__ Y, int ldy, int offy,
                           const float* __restrict__ ssum,
                           const float* __restrict__ sssq,
                           int Co, long rows, float invcnt, int act)
{
    long i = blockIdx.x * (long)blockDim.x + threadIdx.x;
    if (i >= rows * Co) return;
    int  o  = (int)(i % Co);
    long rn = i / Co;
    int  inst = (int)(rn / NP);
    float mu  = ssum[inst * 1024 + o] * invcnt;
    float var = sssq[inst * 1024 + o] * invcnt - mu * mu;
    float v = (X[rn * ldx + offx + o] - mu) * rsqrtf(var + EPSI);
    if (act == 1) v = (v >= 0.f) ? v : 0.2f * v;
    else          v = (v > 0.f)  ? v : 0.f;
    Y[rn * ldy + offy + o] = v;
}

// ======================= attention permutes =======================
__global__ void k_perm_qk_b(const float* __restrict__ raw, float scale,
                            __nv_bfloat16* __restrict__ H, __nv_bfloat16* __restrict__ L)
{
    long i = blockIdx.x * (long)blockDim.x + threadIdx.x;
    if (i >= (long)M4 * 256) return;
    int c = (int)(i % 256); long bn = i / 256;
    int n = (int)(bn % NP); int b = (int)(bn / NP);
    int h = c & 3, dd = c >> 2;
    long oi = (((long)b * 4 + h) * NP + n) * 64 + dd;
    __nv_bfloat16 hi, lo;
    split2(raw[i] * scale, hi, lo);
    H[oi] = hi; L[oi] = lo;
}
__global__ void k_perm_v_b(const float* __restrict__ raw,
                           __nv_bfloat16* __restrict__ H, __nv_bfloat16* __restrict__ L)
{
    long i = blockIdx.x * (long)blockDim.x + threadIdx.x;
    if (i >= (long)M4 * 256) return;
    int c = (int)(i % 256); long bn = i / 256;
    int n = (int)(bn % NP); int b = (int)(bn / NP);
    int h = c & 3, dd = c >> 2;
    long oi = (((long)b * 4 + h) * 64 + dd) * NP + n;
    __nv_bfloat16 hi, lo;
    split2(raw[i], hi, lo);
    H[oi] = hi; L[oi] = lo;
}
__global__ void k_perm_o_b(const float* __restrict__ OHp,
                           __nv_bfloat16* __restrict__ H, __nv_bfloat16* __restrict__ L)
{
    long i = blockIdx.x * (long)blockDim.x + threadIdx.x;
    if (i >= (long)M4 * 256) return;
    int c = (int)(i % 256); long bn = i / 256;
    int n = (int)(bn % NP); int b = (int)(bn / NP);
    int h = c & 3, dd = c >> 2;
    __nv_bfloat16 hi, lo;
    split2(OHp[(((long)b * 4 + h) * NP + n) * 64 + dd], hi, lo);
    H[i] = hi; L[i] = lo;
}

// ======================= host orchestration =======================
#define SMEM128 (2 * 128 * 144 + 2 * 128 * 144)
#define SMEM64  (2 * 128 * 144 + 2 * 64 * 144)

static void tcg(const __nv_bfloat16* AH, const __nv_bfloat16* AL, long lda, long sA,
                const __nv_bfloat16* WH, const __nv_bfloat16* WL, long ldw, long sW,
                const float* bias, float alpha,
                float* C, int ldc, long sC, int M, int Nout, int K, int Z)
{
    if (Nout % 128 == 0) {
        dim3 g(Nout / 128, M / 128, Z);
        mma_gemm<128><<<g, 256, SMEM128>>>(AH, AL, lda, sA, WH, WL, ldw, sW,
                                           bias, alpha, C, ldc, sC, K);
    } else {
        dim3 g(Nout / 64, M / 128, Z);
        mma_gemm<64><<<g, 256, SMEM64>>>(AH, AL, lda, sA, WH, WL, ldw, sW,
                                         bias, alpha, C, ldc, sC, K);
    }
}

#define GSA(sym, var, type) cudaGetSymbolAddress(&pv, sym); type* var = (type*)pv
#define CVT(src, lda, K, total, H, L) \
    k_cvt<<<(int)(((total) / 4 + 255) / 256), 256>>>(src, lda, K, total, H, L)

extern "C" void kernel_launch(void* const* d_in, const int* in_sizes, int n_in,
                              void* d_out, int out_size)
{
    const float* coords1 = (const float*)d_in[0];
    const float* feats1  = (const float*)d_in[1];
    const float* coords2 = (const float*)d_in[2];
    const float* feats2  = (const float*)d_in[3];
    const float* gW1 = (const float*)d_in[4];
    const float* gW2 = (const float*)d_in[5];
    const float* gW3 = (const float*)d_in[6];
    const float* Wq  = (const float*)d_in[7];  const float* bq  = (const float*)d_in[8];
    const float* Wk  = (const float*)d_in[9];  const float* bk  = (const float*)d_in[10];
    const float* Wv  = (const float*)d_in[11]; const float* bv  = (const float*)d_in[12];
    const float* Wo  = (const float*)d_in[13]; const float* bo  = (const float*)d_in[14];
    const float* Wm1 = (const float*)d_in[15]; const float* bm1 = (const float*)d_in[16];
    const float* Wm2 = (const float*)d_in[17]; const float* bm2 = (const float*)d_in[18];
    float* out = (float*)d_out;

    static int attr_set = 0;
    if (!attr_set) {
        cudaFuncSetAttribute(mma_gemm<128>, cudaFuncAttributeMaxDynamicSharedMemorySize, SMEM128);
        cudaFuncSetAttribute(mma_gemm<64>,  cudaFuncAttributeMaxDynamicSharedMemorySize, SMEM64);
        cudaFuncSetAttribute(k_flash,       cudaFuncAttributeMaxDynamicSharedMemorySize, FA_SMEM);
        attr_set = 1;
    }

    void* pv;
    GSA(d_FE,  FEb, float);
    GSA(d_KN,  KNb, int);
    GSA(d_CC,  CCp, float);
    GSA(d_PQ,  PQp, float);
    GSA(d_MX,  MXp, float);
    GSA(d_OH,  OHp, float);
    GSA(d_STT, STp, float);
    GSA(d_AH,  AH, __nv_bfloat16);  GSA(d_AL,  AL, __nv_bfloat16);
    GSA(d_WH,  WH, __nv_bfloat16);  GSA(d_WL,  WL, __nv_bfloat16);
    GSA(d_WQH, WQH, __nv_bfloat16); GSA(d_WQL, WQL, __nv_bfloat16);
    GSA(d_WKH, WKH, __nv_bfloat16); GSA(d_WKL, WKL, __nv_bfloat16);
    GSA(d_WVH, WVH, __nv_bfloat16); GSA(d_WVL, WVL, __nv_bfloat16);
    GSA(d_WOH, WOH, __nv_bfloat16); GSA(d_WOL, WOL, __nv_bfloat16);
    GSA(d_WM1H, WM1H, __nv_bfloat16); GSA(d_WM1L, WM1L, __nv_bfloat16);
    GSA(d_WM2H, WM2H, __nv_bfloat16); GSA(d_WM2L, WM2L, __nv_bfloat16);
    GSA(d_QHH, QHH, __nv_bfloat16); GSA(d_QHL, QHL, __nv_bfloat16);
    GSA(d_KHH, KHH, __nv_bfloat16); GSA(d_KHL, KHL, __nv_bfloat16);
    GSA(d_VTH, VTH, __nv_bfloat16); GSA(d_VTL, VTL, __nv_bfloat16);
    float* SUM = STp;
    float* SSQ = STp + 4 * 1024;
    float* FE[2] = { FEb, FEb + (long)M4 * 256 };

    const int EWB = 256;
    dim3 tb(32, 8);

    k_transpose<<<dim3(NP / 32, 256 / 32, BB), tb>>>(feats1, FE[0], 256, NP);
    k_transpose<<<dim3(NP / 32, 256 / 32, BB), tb>>>(feats2, FE[1], 256, NP);
    k_knn<<<BB * NP, 256>>>(coords1, KNb);
    k_knn<<<BB * NP, 256>>>(coords2, KNb + (long)M4 * KNB);

    const long R8 = M8;   // 8192 rows (both clouds)
    const long R4 = M4;   // 4096 rows

    for (int li = 0; li < 4; li++) {
        int i = li / 2;
        if ((li & 1) == 0) {
            // ---------------- GCN layer i (both clouds batched) ----------------
            k_copy<<<(int)((R8 * 256 + EWB - 1) / EWB), EWB>>>(FEb, 256, CCp, 1024, R8, 256);
            // sublayer 1
            CVT(FEb, 256, 256, R8 * 256, AH, AL);
            k_prepw_b<<<(256 * 256 + 255) / 256, 256>>>(gW1 + (long)i * 256 * 512, WH, WL, 256, 256);
            tcg(AH, AL, 256, 0, WH, WL, 256, 0, nullptr, 1.f, PQp, 512, 0, (int)R8, 512, 256, 1);
            cudaMemsetAsync(STp, 0, sizeof(float) * 2 * 4 * 1024, 0);
            k_edge<<<(int)R8, 256>>>(PQp, KNb, MXp, SUM, SSQ, 256);
            k_norm_act<<<(int)((R8 * 256 + EWB - 1) / EWB), EWB>>>(MXp, 256, 0, CCp, 1024, 256,
                                                                   SUM, SSQ, 256, R8, 1.f / 32768.f, 1);
            // sublayer 2
            CVT(CCp + 256, 1024, 256, R8 * 256, AH, AL);
            k_prepw_b<<<(512 * 256 + 255) / 256, 256>>>(gW2 + (long)i * 512 * 512, WH, WL, 512, 256);
            tcg(AH, AL, 256, 0, WH, WL, 256, 0, nullptr, 1.f, PQp, 1024, 0, (int)R8, 1024, 256, 1);
            cudaMemsetAsync(STp, 0, sizeof(float) * 2 * 4 * 1024, 0);
            k_edge<<<(int)R8, 256>>>(PQp, KNb, MXp, SUM, SSQ, 512);
            k_norm_act<<<(int)((R8 * 512 + EWB - 1) / EWB), EWB>>>(MXp, 512, 0, CCp, 1024, 512,
                                                                   SUM, SSQ, 512, R8, 1.f / 32768.f, 1);
            // W3 on concat (1024 ch)
            CVT(CCp, 1024, 1024, R8 * 1024, AH, AL);
            CVT(gW3 + (long)i * 256 * 1024, 1024, 1024, (long)256 * 1024, WH, WL);
            tcg(AH, AL, 1024, 0, WH, WL, 1024, 0, nullptr, 1.f, MXp, 256, 0, (int)R8, 256, 1024, 1);
            cudaMemsetAsync(STp, 0, sizeof(float) * 2 * 4 * 1024, 0);
            k_colsum<<<(int)(R8 / 128), 256>>>(MXp, 256, SUM, SSQ, 256);
            k_norm_act<<<(int)((R8 * 256 + EWB - 1) / EWB), EWB>>>(MXp, 256, 0, FEb, 256, 0,
                                                                   SUM, SSQ, 256, R8, 1.f / (float)NP, 1);
        } else {
            // ---------------- cross-attention layer i ----------------
            // weight splits once per layer
            CVT(Wq  + (long)i * 65536,  256, 256, 65536,  WQH, WQL);
            CVT(Wk  + (long)i * 65536,  256, 256, 65536,  WKH, WKL);
            CVT(Wv  + (long)i * 65536,  256, 256, 65536,  WVH, WVL);
            CVT(Wo  + (long)i * 65536,  256, 256, 65536,  WOH, WOL);
            CVT(Wm1 + (long)i * 262144, 512, 512, 262144, WM1H, WM1L);
            CVT(Wm2 + (long)i * 131072, 512, 512, 131072, WM2H, WM2L);
            for (int a = 0; a < 2; a++) {
                const float* f1p = FE[a];
                const float* f2p = FE[1 - a];
                long tot = R4 * 256;
                // Q projection (A = f1)
                CVT(f1p, 256, 256, tot, AH, AL);
                tcg(AH, AL, 256, 0, WQH, WQL, 256, 0, bq + (long)i * 256, 1.f, MXp, 256, 0, (int)R4, 256, 256, 1);
                k_perm_qk_b<<<(int)((tot + EWB - 1) / EWB), EWB>>>(MXp, 0.125f, QHH, QHL);
                // K / V projections (A = f2)
                CVT(f2p, 256, 256, tot, AH, AL);
                tcg(AH, AL, 256, 0, WKH, WKL, 256, 0, bk + (long)i * 256, 1.f, MXp, 256, 0, (int)R4, 256, 256, 1);
                k_perm_qk_b<<<(int)((tot + EWB - 1) / EWB), EWB>>>(MXp, 1.f, KHH, KHL);
                tcg(AH, AL, 256, 0, WVH, WVL, 256, 0, bv + (long)i * 256, 1.f, MXp, 256, 0, (int)R4, 256, 256, 1);
                k_perm_v_b<<<(int)((tot + EWB - 1) / EWB), EWB>>>(MXp, VTH, VTL);
                // fused attention
                k_flash<<<dim3(16, 8), 256, FA_SMEM>>>(QHH, QHL, KHH, KHL, VTH, VTL, OHp);
                k_perm_o_b<<<(int)((tot + EWB - 1) / EWB), EWB>>>(OHp, AH, AL);
                // concat [f1, Wo(attn)+bo] -> CC (512 wide)
                k_copy<<<(int)((tot + EWB - 1) / EWB), EWB>>>(f1p, 256, CCp, 512, R4, 256);
                tcg(AH, AL, 256, 0, WOH, WOL, 256, 0, bo + (long)i * 256, 1.f, CCp + 256, 512, 0, (int)R4, 256, 256, 1);
                // Wm1 -> inorm -> relu -> Wm2
                CVT(CCp, 512, 512, R4 * 512, AH, AL);
                tcg(AH, AL, 512, 0, WM1H, WM1L, 512, 0, bm1 + (long)i * 512, 1.f, PQp, 512, 0, (int)R4, 512, 512, 1);
                cudaMemsetAsync(STp, 0, sizeof(float) * 2 * 4 * 1024, 0);
                k_colsum<<<(int)(R4 / 128), 256>>>(PQp, 512, SUM, SSQ, 512);
                k_norm_act<<<(int)((R4 * 512 + EWB - 1) / EWB), EWB>>>(PQp, 512, 0, PQp, 512, 0,
                                                                       SUM, SSQ, 512, R4, 1.f / (float)NP, 2);
                CVT(PQp, 512, 512, R4 * 512, AH, AL);
                tcg(AH, AL, 512, 0, WM2H, WM2L, 512, 0, bm2 + (long)i * 256, 1.f, FE[a], 256, 0, (int)R4, 256, 512, 1);
            }
        }
    }

    k_transpose<<<dim3(256 / 32, NP / 32, BB), tb>>>(FE[0], out, NP, 256);
    k_transpose<<<dim3(256 / 32, NP / 32, BB), tb>>>(FE[1], out + (long)M4 * 256, NP, 256);
}

// round 5
// speedup vs baseline: 2.2335x; 1.1243x over previous
#include <cuda_runtime.h>
#include <cuda_bf16.h>
#include <cstdint>

#define BB   2
#define NP   2048
#define KNB  16
#define EPSI 1e-5f
#define M4   (BB*NP)        // 4096
#define M8   (2*BB*NP)      // 8192

typedef __nv_bfloat16 bf;

// ======================= helpers =======================
__device__ __forceinline__ void split2(float x, bf& h, bf& l){
    h = __float2bfloat16(x);
    l = __float2bfloat16(x - __bfloat162float(h));
}
__device__ __forceinline__ uint32_t packbf(bf a, bf b){
    return ((uint32_t)__bfloat16_as_ushort(b) << 16) | (uint32_t)__bfloat16_as_ushort(a);
}
__device__ __forceinline__ uint32_t packsplit(float a, float b, uint32_t& lo){
    bf ha, la, hb, lb;
    split2(a, ha, la); split2(b, hb, lb);
    lo = packbf(la, lb);
    return packbf(ha, hb);
}

#define MMA16816(d, a, b) \
    asm volatile("mma.sync.aligned.m16n8k16.row.col.f32.bf16.bf16.f32 " \
        "{%0,%1,%2,%3}, {%4,%5,%6,%7}, {%8,%9}, {%0,%1,%2,%3};" \
        : "+f"((d)[0]), "+f"((d)[1]), "+f"((d)[2]), "+f"((d)[3]) \
        : "r"((a)[0]), "r"((a)[1]), "r"((a)[2]), "r"((a)[3]), \
          "r"((b)[0]), "r"((b)[1]))

// ======================= device scratch =======================
__device__ __align__(16) float d_FE [M8*256];
__device__ int   d_KN [M8*KNB];
__device__ __align__(16) float d_PQ [M8*1024];
__device__ __align__(16) float d_MX [M8*512];
__device__ float d_STT[2*4*1024];
__device__ float d_BIAS[3*256];
__device__ __align__(16) bf d_AH [M8*1024];
__device__ __align__(16) bf d_AL [M8*1024];
__device__ __align__(16) bf d_WH [1024*256];
__device__ __align__(16) bf d_WL [1024*256];
__device__ __align__(16) bf d_WQH[256*256],  d_WQL[256*256];
__device__ __align__(16) bf d_WKVH[512*256], d_WKVL[512*256];
__device__ __align__(16) bf d_WOH[256*256],  d_WOL[256*256];
__device__ __align__(16) bf d_WM1H[512*512], d_WM1L[512*512];
__device__ __align__(16) bf d_WM2H[256*512], d_WM2L[256*512];
__device__ __align__(16) bf d_QHH[M4*256], d_QHL[M4*256];
__device__ __align__(16) bf d_KVH[M4*512], d_KVL[M4*512];
__device__ __align__(16) bf d_VTH[M4*256], d_VTL[M4*256];
__device__ __align__(16) bf d_OHH[M4*256], d_OHL[M4*256];

// ======================= transpose (fp32) =======================
__global__ void k_transpose(const float* __restrict__ in, float* __restrict__ out,
                            int R, int Cc)
{
    __shared__ float t[32][33];
    int b  = blockIdx.z;
    const float* ip = in  + (long)b * R * Cc;
    float*       op = out + (long)b * R * Cc;
    int c0 = blockIdx.x * 32, r0 = blockIdx.y * 32;
    for (int i = threadIdx.y; i < 32; i += 8)
        t[i][threadIdx.x] = ip[(long)(r0 + i) * Cc + c0 + threadIdx.x];
    __syncthreads();
    for (int i = threadIdx.y; i < 32; i += 8)
        op[(long)(c0 + i) * R + r0 + threadIdx.x] = t[threadIdx.x][i];
}

// ======================= kNN =======================
__global__ void __launch_bounds__(256) k_knn(const float* __restrict__ coords,
                                             int* __restrict__ knn)
{
    __shared__ float sx[NP], sy[NP], sz[NP], sd[NP];
    __shared__ float wv[8];
    __shared__ int   wi[8];
    int b = blockIdx.x / NP;
    int n = blockIdx.x % NP;
    const float* cb = coords + (long)b * 3 * NP;
    for (int j = threadIdx.x; j < NP; j += 256) {
        sx[j] = cb[j]; sy[j] = cb[NP + j]; sz[j] = cb[2 * NP + j];
    }
    __syncthreads();
    float xn = sx[n], yn = sy[n], zn = sz[n];
    float sqn = xn*xn + yn*yn + zn*zn;
    for (int j = threadIdx.x; j < NP; j += 256) {
        float x = sx[j], y = sy[j], z = sz[j];
        float d = sqn + (x*x + y*y + z*z) - 2.f * (xn*x + yn*y + zn*z);
        sd[j] = (j == n) ? 3.4e38f : d;
    }
    __syncthreads();
    int lane = threadIdx.x & 31, warp = threadIdx.x >> 5;
    for (int r = 0; r < KNB; r++) {
        float best = 3.0e38f; int bi = NP;
        for (int j = threadIdx.x; j < NP; j += 256) {
            float v = sd[j];
            if (v < best) { best = v; bi = j; }
        }
        #pragma unroll
        for (int off = 16; off; off >>= 1) {
            float ov = __shfl_down_sync(0xffffffffu, best, off);
            int   oi = __shfl_down_sync(0xffffffffu, bi,   off);
            if (ov < best || (ov == best && oi < bi)) { best = ov; bi = oi; }
        }
        if (lane == 0) { wv[warp] = best; wi[warp] = bi; }
        __syncthreads();
        if (threadIdx.x == 0) {
            float fb = wv[0]; int fi = wi[0];
            for (int w = 1; w < 8; w++)
                if (wv[w] < fb || (wv[w] == fb && wi[w] < fi)) { fb = wv[w]; fi = wi[w]; }
            knn[((long)b * NP + n) * KNB + r] = fi;
            sd[fi] = 3.4e38f;
        }
        __syncthreads();
    }
}

// ======================= HMMA GEMM =======================
// C[m,o] = alpha*sum_k (AH+AL)[m,k]*(WH+WL)[o,k] + bias
// EPI 0: fp32 C. EPI 1: split bf16 hi/lo to OH/OL.
// tile 128x128x64, 256 threads, all Nout multiples of 128.
template <int EPI>
__global__ void __launch_bounds__(256) mma_gemm(
    const bf* __restrict__ AH, const bf* __restrict__ AL, long lda,
    const bf* __restrict__ WH, const bf* __restrict__ WL, long ldw,
    const float* __restrict__ bias, const float* __restrict__ bias2, float alpha,
    float* __restrict__ C, bf* __restrict__ OH, bf* __restrict__ OL,
    int ldc, int K)
{
    extern __shared__ __align__(16) char smem[];
    char* sAh = smem;
    char* sAl = smem + 128 * 144;
    char* sWh = smem + 2 * 128 * 144;
    char* sWl = smem + 3 * 128 * 144;

    int tid = threadIdx.x, wid = tid >> 5, lane = tid & 31;
    int g = lane >> 2, tg = lane & 3;
    int wm = (wid >> 2) * 64;
    int wn = (wid & 3) * 32;

    long m0 = (long)blockIdx.y * 128;
    int  n0 = blockIdx.x * 128;
    const bf* pAH = AH + m0 * lda;
    const bf* pAL = AL + m0 * lda;
    const bf* pWH = WH + (long)n0 * ldw;
    const bf* pWL = WL + (long)n0 * ldw;

    float acc[4][4][4];
    #pragma unroll
    for (int mt = 0; mt < 4; mt++)
        #pragma unroll
        for (int nt = 0; nt < 4; nt++)
            #pragma unroll
            for (int q = 0; q < 4; q++) acc[mt][nt][q] = 0.f;

    for (int k0 = 0; k0 < K; k0 += 64) {
        #pragma unroll
        for (int it = 0; it < 4; it++) {
            int i = tid + it * 256;
            int r = i >> 3, q = i & 7;
            *(uint4*)(sAh + r * 144 + q * 16) = *(const uint4*)(pAH + (long)r * lda + k0 + q * 8);
            *(uint4*)(sAl + r * 144 + q * 16) = *(const uint4*)(pAL + (long)r * lda + k0 + q * 8);
            *(uint4*)(sWh + r * 144 + q * 16) = *(const uint4*)(pWH + (long)r * ldw + k0 + q * 8);
            *(uint4*)(sWl + r * 144 + q * 16) = *(const uint4*)(pWL + (long)r * ldw + k0 + q * 8);
        }
        __syncthreads();

        #pragma unroll
        for (int ks = 0; ks < 4; ks++) {
            int kb = ks * 16;
            uint32_t ah[4][4], al[4][4];
            #pragma unroll
            for (int mt = 0; mt < 4; mt++) {
                int roff = (wm + mt * 16 + g) * 144 + (kb + tg * 2) * 2;
                ah[mt][0] = *(const uint32_t*)(sAh + roff);
                ah[mt][1] = *(const uint32_t*)(sAh + roff + 8 * 144);
                ah[mt][2] = *(const uint32_t*)(sAh + roff + 16);
                ah[mt][3] = *(const uint32_t*)(sAh + roff + 8 * 144 + 16);
                al[mt][0] = *(const uint32_t*)(sAl + roff);
                al[mt][1] = *(const uint32_t*)(sAl + roff + 8 * 144);
                al[mt][2] = *(const uint32_t*)(sAl + roff + 16);
                al[mt][3] = *(const uint32_t*)(sAl + roff + 8 * 144 + 16);
            }
            uint32_t bh[4][2], bl[4][2];
            #pragma unroll
            for (int nt = 0; nt < 4; nt++) {
                int roff = (wn + nt * 8 + g) * 144 + (kb + tg * 2) * 2;
                bh[nt][0] = *(const uint32_t*)(sWh + roff);
                bh[nt][1] = *(const uint32_t*)(sWh + roff + 16);
                bl[nt][0] = *(const uint32_t*)(sWl + roff);
                bl[nt][1] = *(const uint32_t*)(sWl + roff + 16);
            }
            #pragma unroll
            for (int mt = 0; mt < 4; mt++)
                #pragma unroll
                for (int nt = 0; nt < 4; nt++) {
                    MMA16816(acc[mt][nt], ah[mt], bh[nt]);
                    MMA16816(acc[mt][nt], ah[mt], bl[nt]);
                    MMA16816(acc[mt][nt], al[mt], bh[nt]);
                }
        }
        __syncthreads();
    }

    #pragma unroll
    for (int mt = 0; mt < 4; mt++) {
        long row = m0 + wm + mt * 16 + g;
        #pragma unroll
        for (int nt = 0; nt < 4; nt++) {
            int col = n0 + wn + nt * 8 + tg * 2;
            float b0 = 0.f, b1 = 0.f;
            if (bias) {
                const float* bp = (bias2 && col >= 256) ? (bias2 - 256) : bias;
                b0 = __ldg(&bp[col]); b1 = __ldg(&bp[col + 1]);
            }
            float v0 = acc[mt][nt][0] * alpha + b0;
            float v1 = acc[mt][nt][1] * alpha + b1;
            float v2 = acc[mt][nt][2] * alpha + b0;
            float v3 = acc[mt][nt][3] * alpha + b1;
            if (EPI == 0) {
                *(float2*)(C + row * (long)ldc + col)       = make_float2(v0, v1);
                *(float2*)(C + (row + 8) * (long)ldc + col) = make_float2(v2, v3);
            } else {
                uint32_t lo0, lo1;
                uint32_t hi0 = packsplit(v0, v1, lo0);
                uint32_t hi1 = packsplit(v2, v3, lo1);
                *(uint32_t*)(OH + row * (long)ldc + col)       = hi0;
                *(uint32_t*)(OL + row * (long)ldc + col)       = lo0;
                *(uint32_t*)(OH + (row + 8) * (long)ldc + col) = hi1;
                *(uint32_t*)(OL + (row + 8) * (long)ldc + col) = lo1;
            }
        }
    }
}

// ======================= fused flash attention =======================
// Q: (bn, 256) ld256 head-blocked bf16 hi/lo (pre-scaled). K: in KV (bn,512) ld512.
// V: (z,dd,n). Out: bf16 hi/lo (bn,256) head-blocked (Wo-input layout).
#define FA_SMEM (2*128*144 + 4*64*144)
__global__ void __launch_bounds__(256) k_flash(
    const bf* __restrict__ QH, const bf* __restrict__ QL,
    const bf* __restrict__ KVH, const bf* __restrict__ KVL,
    const bf* __restrict__ VH, const bf* __restrict__ VL,
    bf* __restrict__ OH, bf* __restrict__ OL)
{
    extern __shared__ __align__(16) char smem[];
    char* sQh = smem;
    char* sQl = smem + 128*144;
    char* sKh = smem + 2*128*144;
    char* sKl = sKh + 64*144;
    char* sVh = sKl + 64*144;
    char* sVl = sVh + 64*144;

    int tid = threadIdx.x, wid = tid >> 5, lane = tid & 31;
    int g = lane >> 2, tg = lane & 3;
    int z = blockIdx.y;
    int b = z >> 2, h = z & 3;
    long q0 = (long)blockIdx.x * 128;
    int wm = wid * 16;

    const bf* pQH = QH + ((long)b * NP + q0) * 256 + h * 64;
    const bf* pQL = QL + ((long)b * NP + q0) * 256 + h * 64;

    #pragma unroll
    for (int it = 0; it < 4; it++) {
        int i = tid + it * 256;
        int r = i >> 3, q = i & 7;
        *(uint4*)(sQh + r * 144 + q * 16) = *(const uint4*)(pQH + (long)r * 256 + q * 8);
        *(uint4*)(sQl + r * 144 + q * 16) = *(const uint4*)(pQL + (long)r * 256 + q * 8);
    }

    float m0 = -3.4e38f, m1 = -3.4e38f, l0 = 0.f, l1 = 0.f;
    float acc[8][4];
    #pragma unroll
    for (int nt = 0; nt < 8; nt++)
        #pragma unroll
        for (int q = 0; q < 4; q++) acc[nt][q] = 0.f;

    for (int c = 0; c < NP / 64; c++) {
        const bf* pKH = KVH + ((long)b * NP + c * 64) * 512 + h * 64;
        const bf* pKL = KVL + ((long)b * NP + c * 64) * 512 + h * 64;
        const bf* pVH = VH + (long)z * 64 * NP + c * 64;
        const bf* pVL = VL + (long)z * 64 * NP + c * 64;
        #pragma unroll
        for (int it = 0; it < 2; it++) {
            int i = tid + it * 256;
            int r = i >> 3, q = i & 7;
            *(uint4*)(sKh + r * 144 + q * 16) = *(const uint4*)(pKH + (long)r * 512 + q * 8);
            *(uint4*)(sKl + r * 144 + q * 16) = *(const uint4*)(pKL + (long)r * 512 + q * 8);
            *(uint4*)(sVh + r * 144 + q * 16) = *(const uint4*)(pVH + (long)r * NP + q * 8);
            *(uint4*)(sVl + r * 144 + q * 16) = *(const uint4*)(pVL + (long)r * NP + q * 8);
        }
        __syncthreads();

        float sacc[8][4];
        #pragma unroll
        for (int nt = 0; nt < 8; nt++)
            #pragma unroll
            for (int q = 0; q < 4; q++) sacc[nt][q] = 0.f;
        #pragma unroll
        for (int kk = 0; kk < 4; kk++) {
            int kb = kk * 16;
            uint32_t aqh[4], aql[4];
            int roff = (wm + g) * 144 + (kb + tg * 2) * 2;
            aqh[0] = *(const uint32_t*)(sQh + roff);
            aqh[1] = *(const uint32_t*)(sQh + roff + 8 * 144);
            aqh[2] = *(const uint32_t*)(sQh + roff + 16);
            aqh[3] = *(const uint32_t*)(sQh + roff + 8 * 144 + 16);
            aql[0] = *(const uint32_t*)(sQl + roff);
            aql[1] = *(const uint32_t*)(sQl + roff + 8 * 144);
            aql[2] = *(const uint32_t*)(sQl + roff + 16);
            aql[3] = *(const uint32_t*)(sQl + roff + 8 * 144 + 16);
            #pragma unroll
            for (int nt = 0; nt < 8; nt++) {
                uint32_t bh[2], bl[2];
                int boff = (nt * 8 + g) * 144 + (kb + tg * 2) * 2;
                bh[0] = *(const uint32_t*)(sKh + boff);
                bh[1] = *(const uint32_t*)(sKh + boff + 16);
                bl[0] = *(const uint32_t*)(sKl + boff);
                bl[1] = *(const uint32_t*)(sKl + boff + 16);
                MMA16816(sacc[nt], aqh, bh);
                MMA16816(sacc[nt], aqh, bl);
                MMA16816(sacc[nt], aql, bh);
            }
        }

        float rmax0 = -3.4e38f, rmax1 = -3.4e38f;
        #pragma unroll
        for (int nt = 0; nt < 8; nt++) {
            rmax0 = fmaxf(rmax0, fmaxf(sacc[nt][0], sacc[nt][1]));
            rmax1 = fmaxf(rmax1, fmaxf(sacc[nt][2], sacc[nt][3]));
        }
        rmax0 = fmaxf(rmax0, __shfl_xor_sync(0xffffffffu, rmax0, 1));
        rmax0 = fmaxf(rmax0, __shfl_xor_sync(0xffffffffu, rmax0, 2));
        rmax1 = fmaxf(rmax1, __shfl_xor_sync(0xffffffffu, rmax1, 1));
        rmax1 = fmaxf(rmax1, __shfl_xor_sync(0xffffffffu, rmax1, 2));
        float mn0 = fmaxf(m0, rmax0), mn1 = fmaxf(m1, rmax1);
        float al0 = __expf(m0 - mn0), al1 = __expf(m1 - mn1);
        m0 = mn0; m1 = mn1;

        float rs0 = 0.f, rs1 = 0.f;
        uint32_t pfh[4][4], pfl[4][4];
        #pragma unroll
        for (int nt = 0; nt < 8; nt++) {
            float p0 = __expf(sacc[nt][0] - mn0);
            float p1 = __expf(sacc[nt][1] - mn0);
            float p2 = __expf(sacc[nt][2] - mn1);
            float p3 = __expf(sacc[nt][3] - mn1);
            rs0 += p0 + p1; rs1 += p2 + p3;
            int kk = nt >> 1, base = (nt & 1) * 2;
            pfh[kk][base]     = packsplit(p0, p1, pfl[kk][base]);
            pfh[kk][base + 1] = packsplit(p2, p3, pfl[kk][base + 1]);
        }
        rs0 += __shfl_xor_sync(0xffffffffu, rs0, 1);
        rs0 += __shfl_xor_sync(0xffffffffu, rs0, 2);
        rs1 += __shfl_xor_sync(0xffffffffu, rs1, 1);
        rs1 += __shfl_xor_sync(0xffffffffu, rs1, 2);
        l0 = l0 * al0 + rs0; l1 = l1 * al1 + rs1;
        #pragma unroll
        for (int nt = 0; nt < 8; nt++) {
            acc[nt][0] *= al0; acc[nt][1] *= al0;
            acc[nt][2] *= al1; acc[nt][3] *= al1;
        }

        #pragma unroll
        for (int kk = 0; kk < 4; kk++) {
            #pragma unroll
            for (int nt = 0; nt < 8; nt++) {
                uint32_t bh[2], bl[2];
                int boff = (nt * 8 + g) * 144 + (kk * 16 + tg * 2) * 2;
                bh[0] = *(const uint32_t*)(sVh + boff);
                bh[1] = *(const uint32_t*)(sVh + boff + 16);
                bl[0] = *(const uint32_t*)(sVl + boff);
                bl[1] = *(const uint32_t*)(sVl + boff + 16);
                MMA16816(acc[nt], pfh[kk], bh);
                MMA16816(acc[nt], pfh[kk], bl);
                MMA16816(acc[nt], pfl[kk], bh);
            }
        }
        __syncthreads();
    }

    float inv0 = 1.f / l0, inv1 = 1.f / l1;
    bf* pOH = OH + ((long)b * NP + q0 + wm) * 256 + h * 64;
    bf* pOL = OL + ((long)b * NP + q0 + wm) * 256 + h * 64;
    #pragma unroll
    for (int nt = 0; nt < 8; nt++) {
        int col = nt * 8 + tg * 2;
        uint32_t lo0, lo1;
        uint32_t hi0 = packsplit(acc[nt][0] * inv0, acc[nt][1] * inv0, lo0);
        uint32_t hi1 = packsplit(acc[nt][2] * inv1, acc[nt][3] * inv1, lo1);
        *(uint32_t*)(pOH + (long)g * 256 + col)       = hi0;
        *(uint32_t*)(pOL + (long)g * 256 + col)       = lo0;
        *(uint32_t*)(pOH + (long)(g + 8) * 256 + col) = hi1;
        *(uint32_t*)(pOL + (long)(g + 8) * 256 + col) = lo1;
    }
}

// ======================= fp32 -> bf16 hi/lo (output stride) =======================
__global__ void k_cvt(const float* __restrict__ src, long ldi, int cols, long total,
                      bf* __restrict__ H, bf* __restrict__ L, long ldo)
{
    long i = ((long)blockIdx.x * blockDim.x + threadIdx.x) * 4;
    if (i >= total) return;
    long r = i / cols; int c = (int)(i - r * cols);
    float4 v = *(const float4*)(src + r * ldi + c);
    uint32_t lo0, lo1;
    uint32_t hi0 = packsplit(v.x, v.y, lo0);
    uint32_t hi1 = packsplit(v.z, v.w, lo1);
    *(uint2*)(H + r * ldo + c) = make_uint2(hi0, hi1);
    *(uint2*)(L + r * ldo + c) = make_uint2(lo0, lo1);
}

// GCN weight prep: stacked [Wa-Wb; Wb]
__global__ void k_prepw_b(const float* __restrict__ W, bf* __restrict__ H,
                          bf* __restrict__ L, int O, int Ci)
{
    long i = blockIdx.x * (long)blockDim.x + threadIdx.x;
    if (i >= (long)O * Ci) return;
    int o = (int)(i / Ci), c = (int)(i % Ci);
    float a  = W[(long)o * 2 * Ci + c];
    float bq = W[(long)o * 2 * Ci + Ci + c];
    bf h, l;
    split2(a - bq, h, l);
    H[(long)o * Ci + c] = h; L[(long)o * Ci + c] = l;
    split2(bq, h, l);
    H[((long)O + o) * Ci + c] = h; L[((long)O + o) * Ci + c] = l;
}

// attention QKV weight prep: row permute (dd,h)->(h,dd), scale, split (+bias)
__global__ void k_prepw_perm(const float* __restrict__ W, float scale,
                             bf* __restrict__ H, bf* __restrict__ L, int roff,
                             const float* __restrict__ bin, float* __restrict__ bout)
{
    int i = blockIdx.x * blockDim.x + threadIdx.x;
    if (i >= 256 * 256) return;
    int o = i >> 8, c = i & 255;
    int op = (o & 3) * 64 + (o >> 2);
    bf h, l;
    split2(W[i] * scale, h, l);
    H[(long)(roff + op) * 256 + c] = h;
    L[(long)(roff + op) * 256 + c] = l;
    if (c == 0) bout[op] = bin[o] * scale;
}

// Wo prep: column permute (input channels reordered to head-blocked)
__global__ void k_prepw_colperm(const float* __restrict__ W,
                                bf* __restrict__ H, bf* __restrict__ L)
{
    int i = blockIdx.x * blockDim.x + threadIdx.x;
    if (i >= 256 * 256) return;
    int o = i >> 8, oc = i & 255;
    int c = (oc & 63) * 4 + (oc >> 6);
    bf h, l;
    split2(W[o * 256 + c], h, l);
    H[i] = h; L[i] = l;
}

// V transpose: KV cols [256,512) (bn, head-blocked) -> (z, dd, n), bf16
__global__ void k_vtrans(const bf* __restrict__ SH, const bf* __restrict__ SL,
                         bf* __restrict__ DH, bf* __restrict__ DL)
{
    __shared__ uint16_t th[32][34], tl[32][34];
    int b = blockIdx.z;
    int hc0 = blockIdx.x * 32;     // head-blocked channel tile
    int n0  = blockIdx.y * 32;
    int tx = threadIdx.x, ty = threadIdx.y;
    for (int i = ty; i < 32; i += 8) {
        long src = ((long)b * NP + n0 + i) * 512 + 256 + hc0 + tx;
        th[i][tx] = ((const uint16_t*)SH)[src];
        tl[i][tx] = ((const uint16_t*)SL)[src];
    }
    __syncthreads();
    for (int i = ty; i < 32; i += 8) {
        int hc = hc0 + i;
        int h = hc >> 6, dd = hc & 63;
        long dst = (((long)b * 4 + h) * 64 + dd) * NP + n0 + tx;
        ((uint16_t*)DH)[dst] = th[tx][i];
        ((uint16_t*)DL)[dst] = tl[tx][i];
    }
}

// ======================= edge gather: max + stats =======================
__global__ void __launch_bounds__(256) k_edge(const float* __restrict__ PQ,
                                              const int* __restrict__ knn,
                                              float* __restrict__ mx,
                                              float* __restrict__ ssum,
                                              float* __restrict__ sssq,
                                              int Co)
{
    __shared__ long nbb[KNB];
    long bn = blockIdx.x;
    int  inst = (int)(bn / NP);
    if (threadIdx.x < KNB) {
        int nb = knn[bn * KNB + threadIdx.x];
        nbb[threadIdx.x] = ((long)inst * NP + nb) * (2 * Co) + Co;
    }
    __syncthreads();
    const float* Prow = PQ + bn * (2 * Co);
    for (int o = threadIdx.x; o < Co; o += 256) {
        float p = Prow[o];
        float mv = -3.4e38f, s = 0.f, ss = 0.f;
        #pragma unroll
        for (int k2 = 0; k2 < KNB; k2++) {
            float v = p + PQ[nbb[k2] + o];
            mv = fmaxf(mv, v); s += v; ss += v * v;
        }
        mx[bn * Co + o] = mv;
        atomicAdd(&ssum[inst * 1024 + o], s);
        atomicAdd(&sssq[inst * 1024 + o], ss);
    }
}

// ======================= per-channel stats =======================
__global__ void __launch_bounds__(256) k_colsum(const float* __restrict__ X, int ldx,
                                                float* __restrict__ ssum,
                                                float* __restrict__ sssq, int Co)
{
    int nch = NP / 128;
    int inst = blockIdx.x / nch;
    int ch   = blockIdx.x % nch;
    long r0 = (long)inst * NP + ch * 128;
    for (int o = threadIdx.x; o < Co; o += 256) {
        float s = 0.f, ss = 0.f;
        for (int r = 0; r < 128; r++) {
            float v = X[(r0 + r) * ldx + o];
            s += v; ss += v * v;
        }
        atomicAdd(&ssum[inst * 1024 + o], s);
        atomicAdd(&sssq[inst * 1024 + o], ss);
    }
}

// ======================= normalize + act -> fp32 =======================
__global__ void k_norm_act(const float* __restrict__ X, int ldx,
                           float* __restrict__ Y, int ldy,
                           const float* __restrict__ ssum,
                           const float* __restrict__ sssq,
                           int Co, long rows, float invcnt, int act)
{
    long i = blockIdx.x * (long)blockDim.x + threadIdx.x;
    if (i >= rows * Co) return;
    int  o  = (int)(i % Co);
    long rn = i / Co;
    int  inst = (int)(rn / NP);
    float mu  = ssum[inst * 1024 + o] * invcnt;
    float var = sssq[inst * 1024 + o] * invcnt - mu * mu;
    float v = (X[rn * ldx + o] - mu) * rsqrtf(var + EPSI);
    if (act == 1) v = (v >= 0.f) ? v : 0.2f * v;
    else          v = (v > 0.f)  ? v : 0.f;
    Y[rn * ldy + o] = v;
}

// ======================= normalize + act -> bf16 hi/lo =======================
__global__ void k_norm_act_split(const float* __restrict__ X, int ldx,
                                 bf* __restrict__ H, bf* __restrict__ L,
                                 int ldy, int offy,
                                 const float* __restrict__ ssum,
                                 const float* __restrict__ sssq,
                                 int Co, long rows, float invcnt, int act)
{
    long i = blockIdx.x * (long)blockDim.x + threadIdx.x;
    if (i >= rows * Co) return;
    int  o  = (int)(i % Co);
    long rn = i / Co;
    int  inst = (int)(rn / NP);
    float mu  = ssum[inst * 1024 + o] * invcnt;
    float var = sssq[inst * 1024 + o] * invcnt - mu * mu;
    float v = (X[rn * ldx + o] - mu) * rsqrtf(var + EPSI);
    if (act == 1) v = (v >= 0.f) ? v : 0.2f * v;
    else          v = (v > 0.f)  ? v : 0.f;
    bf h, l;
    split2(v, h, l);
    H[rn * ldy + offy + o] = h;
    L[rn * ldy + offy + o] = l;
}

// ======================= host =======================
#define GEMM_SMEM (4 * 128 * 144)

static void gemm_f(const bf* AH, const bf* AL, long lda,
                   const bf* WH, const bf* WL, long ldw,
                   const float* bias, float* C, int ldc, int M, int Nout, int K)
{
    dim3 g(Nout / 128, M / 128);
    mma_gemm<0><<<g, 256, GEMM_SMEM>>>(AH, AL, lda, WH, WL, ldw, bias, nullptr, 1.f,
                                       C, nullptr, nullptr, ldc, K);
}
static void gemm_s(const bf* AH, const bf* AL, long lda,
                   const bf* WH, const bf* WL, long ldw,
                   const float* bias, const float* bias2,
                   bf* OH, bf* OL, int ldc, int M, int Nout, int K)
{
    dim3 g(Nout / 128, M / 128);
    mma_gemm<1><<<g, 256, GEMM_SMEM>>>(AH, AL, lda, WH, WL, ldw, bias, bias2, 1.f,
                                       nullptr, OH, OL, ldc, K);
}

#define GSA(sym, var, type) cudaGetSymbolAddress(&pv, sym); type* var = (type*)pv
#define CVT(src, ldi, cols, total, H, L, ldo) \
    k_cvt<<<(int)(((total) / 4 + 255) / 256), 256>>>(src, ldi, cols, total, H, L, ldo)

extern "C" void kernel_launch(void* const* d_in, const int* in_sizes, int n_in,
                              void* d_out, int out_size)
{
    const float* coords1 = (const float*)d_in[0];
    const float* coords2 = (const float*)d_in[2];
    const float* feats1  = (const float*)d_in[1];
    const float* feats2  = (const float*)d_in[3];
    const float* gW1 = (const float*)d_in[4];
    const float* gW2 = (const float*)d_in[5];
    const float* gW3 = (const float*)d_in[6];
    const float* Wq  = (const float*)d_in[7];  const float* bq  = (const float*)d_in[8];
    const float* Wk  = (const float*)d_in[9];  const float* bk  = (const float*)d_in[10];
    const float* Wv  = (const float*)d_in[11]; const float* bv  = (const float*)d_in[12];
    const float* Wo  = (const float*)d_in[13]; const float* bo  = (const float*)d_in[14];
    const float* Wm1 = (const float*)d_in[15]; const float* bm1 = (const float*)d_in[16];
    const float* Wm2 = (const float*)d_in[17]; const float* bm2 = (const float*)d_in[18];
    float* out = (float*)d_out;

    static int attr_set = 0;
    if (!attr_set) {
        cudaFuncSetAttribute(mma_gemm<0>, cudaFuncAttributeMaxDynamicSharedMemorySize, GEMM_SMEM);
        cudaFuncSetAttribute(mma_gemm<1>, cudaFuncAttributeMaxDynamicSharedMemorySize, GEMM_SMEM);
        cudaFuncSetAttribute(k_flash,     cudaFuncAttributeMaxDynamicSharedMemorySize, FA_SMEM);
        attr_set = 1;
    }

    void* pv;
    GSA(d_FE,  FEb, float);
    GSA(d_KN,  KNb, int);
    GSA(d_PQ,  PQp, float);
    GSA(d_MX,  MXp, float);
    GSA(d_STT, STp, float);
    GSA(d_BIAS, BP, float);
    GSA(d_AH,  AH, bf);   GSA(d_AL,  AL, bf);
    GSA(d_WH,  WH, bf);   GSA(d_WL,  WL, bf);
    GSA(d_WQH, WQH, bf);  GSA(d_WQL, WQL, bf);
    GSA(d_WKVH, WKVH, bf); GSA(d_WKVL, WKVL, bf);
    GSA(d_WOH, WOH, bf);  GSA(d_WOL, WOL, bf);
    GSA(d_WM1H, WM1H, bf); GSA(d_WM1L, WM1L, bf);
    GSA(d_WM2H, WM2H, bf); GSA(d_WM2L, WM2L, bf);
    GSA(d_QHH, QHH, bf);  GSA(d_QHL, QHL, bf);
    GSA(d_KVH, KVH, bf);  GSA(d_KVL, KVL, bf);
    GSA(d_VTH, VTH, bf);  GSA(d_VTL, VTL, bf);
    GSA(d_OHH, OHH, bf);  GSA(d_OHL, OHL, bf);
    float* SUM = STp;
    float* SSQ = STp + 4 * 1024;
    float* BQP = BP;            // permuted, scaled biases
    float* BKP = BP + 256;
    float* BVP = BP + 512;
    float* FE[2] = { FEb, FEb + (long)M4 * 256 };
    // attention scratch inside d_AH/d_AL: F1CC = rows M4 x 512; F2 dense after it
    bf* F1H = AH;               bf* F1L = AL;
    bf* F2H = AH + (long)M4 * 512;
    bf* F2L = AL + (long)M4 * 512;

    const int EWB = 256;
    dim3 tb(32, 8);

    k_transpose<<<dim3(NP / 32, 256 / 32, BB), tb>>>(feats1, FE[0], 256, NP);
    k_transpose<<<dim3(NP / 32, 256 / 32, BB), tb>>>(feats2, FE[1], 256, NP);
    k_knn<<<BB * NP, 256>>>(coords1, KNb);
    k_knn<<<BB * NP, 256>>>(coords2, KNb + (long)M4 * KNB);

    const long R8 = M8, R4 = M4;

    for (int li = 0; li < 4; li++) {
        int i = li / 2;
        if ((li & 1) == 0) {
            // ---------------- GCN layer i (both clouds batched) ----------------
            CVT(FEb, 256, 256, R8 * 256, AH, AL, 1024);                 // slot 0
            k_prepw_b<<<(256 * 256 + 255) / 256, 256>>>(gW1 + (long)i * 256 * 512, WH, WL, 256, 256);
            gemm_f(AH, AL, 1024, WH, WL, 256, nullptr, PQp, 512, (int)R8, 512, 256);
            cudaMemsetAsync(STp, 0, sizeof(float) * 2 * 4 * 1024, 0);
            k_edge<<<(int)R8, 256>>>(PQp, KNb, MXp, SUM, SSQ, 256);
            k_norm_act_split<<<(int)((R8 * 256 + EWB - 1) / EWB), EWB>>>(
                MXp, 256, AH, AL, 1024, 256, SUM, SSQ, 256, R8, 1.f / 32768.f, 1);
            k_prepw_b<<<(512 * 256 + 255) / 256, 256>>>(gW2 + (long)i * 512 * 512, WH, WL, 512, 256);
            gemm_f(AH + 256, AL + 256, 1024, WH, WL, 256, nullptr, PQp, 1024, (int)R8, 1024, 256);
            cudaMemsetAsync(STp, 0, sizeof(float) * 2 * 4 * 1024, 0);
            k_edge<<<(int)R8, 256>>>(PQp, KNb, MXp, SUM, SSQ, 512);
            k_norm_act_split<<<(int)((R8 * 512 + EWB - 1) / EWB), EWB>>>(
                MXp, 512, AH, AL, 1024, 512, SUM, SSQ, 512, R8, 1.f / 32768.f, 1);
            CVT(gW3 + (long)i * 256 * 1024, 1024, 1024, (long)256 * 1024, WH, WL, 1024);
            gemm_f(AH, AL, 1024, WH, WL, 1024, nullptr, MXp, 256, (int)R8, 256, 1024);
            cudaMemsetAsync(STp, 0, sizeof(float) * 2 * 4 * 1024, 0);
            k_colsum<<<(int)(R8 / 128), 256>>>(MXp, 256, SUM, SSQ, 256);
            k_norm_act<<<(int)((R8 * 256 + EWB - 1) / EWB), EWB>>>(
                MXp, 256, FEb, 256, SUM, SSQ, 256, R8, 1.f / (float)NP, 1);
        } else {
            // ---------------- cross-attention layer i ----------------
            k_prepw_perm<<<256, 256>>>(Wq + (long)i * 65536, 0.125f, WQH, WQL, 0,
                                       bq + (long)i * 256, BQP);
            k_prepw_perm<<<256, 256>>>(Wk + (long)i * 65536, 1.f, WKVH, WKVL, 0,
                                       bk + (long)i * 256, BKP);
            k_prepw_perm<<<256, 256>>>(Wv + (long)i * 65536, 1.f, WKVH, WKVL, 256,
                                       bv + (long)i * 256, BVP);
            k_prepw_colperm<<<256, 256>>>(Wo + (long)i * 65536, WOH, WOL);
            CVT(Wm1 + (long)i * 262144, 512, 512, (long)262144, WM1H, WM1L, 512);
            CVT(Wm2 + (long)i * 131072, 512, 512, (long)131072, WM2H, WM2L, 512);
            for (int a = 0; a < 2; a++) {
                const float* f1p = FE[a];
                const float* f2p = FE[1 - a];
                // f1 split into F1CC slot 0 (ld 512)
                CVT(f1p, 256, 256, R4 * 256, F1H, F1L, 512);
                // Q = f1 @ Wq' (scaled, permuted) -> bf16 head-blocked
                gemm_s(F1H, F1L, 512, WQH, WQL, 256, BQP, nullptr,
                       QHH, QHL, 256, (int)R4, 256, 256);
                // f2 split dense, K|V stacked projection
                CVT(f2p, 256, 256, R4 * 256, F2H, F2L, 256);
                gemm_s(F2H, F2L, 256, WKVH, WKVL, 256, BKP, BVP,
                       KVH, KVL, 512, (int)R4, 512, 256);
                k_vtrans<<<dim3(8, NP / 32, BB), tb>>>(KVH, KVL, VTH, VTL);
                // fused attention -> Wo-input layout bf16
                k_flash<<<dim3(16, 8), 256, FA_SMEM>>>(QHH, QHL, KVH, KVL, VTH, VTL, OHH, OHL);
                // Wo projection -> F1CC slot 256
                gemm_s(OHH, OHL, 256, WOH, WOL, 256, bo + (long)i * 256, nullptr,
                       F1H + 256, F1L + 256, 512, (int)R4, 256, 256);
                // Wm1 -> inorm -> relu (split) -> Wm2
                gemm_f(F1H, F1L, 512, WM1H, WM1L, 512, bm1 + (long)i * 512,
                       PQp, 512, (int)R4, 512, 512);
                cudaMemsetAsync(STp, 0, sizeof(float) * 2 * 4 * 1024, 0);
                k_colsum<<<(int)(R4 / 128), 256>>>(PQp, 512, SUM, SSQ, 512);
                k_norm_act_split<<<(int)((R4 * 512 + EWB - 1) / EWB), EWB>>>(
                    PQp, 512, F1H, F1L, 512, 0, SUM, SSQ, 512, R4, 1.f / (float)NP, 2);
                gemm_f(F1H, F1L, 512, WM2H, WM2L, 512, bm2 + (long)i * 256,
                       FE[a], 256, (int)R4, 256, 512);
            }
        }
    }

    k_transpose<<<dim3(256 / 32, NP / 32, BB), tb>>>(FE[0], out, NP, 256);
    k_transpose<<<dim3(256 / 32, NP / 32, BB), tb>>>(FE[1], out + (long)M4 * 256, NP, 256);
}